// round 1
// baseline (speedup 1.0000x reference)
#include <cuda_runtime.h>
#include <math.h>

#define B_ 8
#define T_ 512
#define C_ 512
#define H_ 8
#define F_ 2048
#define WIN_ 10

#define ELT_X (B_*C_*T_)      /* 2,097,152  */
#define ELT_H (B_*F_*T_)      /* 8,388,608  */
#define ELT_P (B_*H_*T_*T_)   /* 16,777,216 */

__device__ float g_pool[(size_t)6*ELT_X + ELT_H + ELT_P];

/* ---------------- elementwise mask ---------------- */
__global__ void k_maskmul(const float* __restrict__ X, const float* __restrict__ mask,
                          float* __restrict__ Y)
{
    int i = blockIdx.x*256 + threadIdx.x;
    int t = i & (T_-1);
    int b = i / (C_*T_);
    Y[i] = X[i] * mask[b*T_ + t];
}

/* ---------------- 1x1 conv (GEMM): Y[b,o,t] = alpha*(sum_c W[o,c] X[b,c,t] + bias[o]) */
__launch_bounds__(128)
__global__ void k_conv1x1(const float* __restrict__ X, const float* __restrict__ Wm,
                          const float* __restrict__ bias, float* __restrict__ Y,
                          int Cin, int Cout, float alpha)
{
    const int t0 = blockIdx.x*128;
    const int o0 = blockIdx.y*64;
    const int b  = blockIdx.z;
    __shared__ float w_sm[16][65];
    __shared__ float x_sm[16][128];
    const int tid = threadIdx.x;
    const int wx = tid & 15, wy = tid >> 4;
    float acc[8][8];
#pragma unroll
    for (int i=0;i<8;i++)
#pragma unroll
        for (int j=0;j<8;j++) acc[i][j]=0.f;

    const float* xb = X + (size_t)b*Cin*T_;
    for (int c0=0;c0<Cin;c0+=16){
#pragma unroll
        for (int r=0;r<8;r++){
            int l = tid + r*128;
            int oo = l>>4, cc = l&15;
            w_sm[cc][oo] = Wm[(size_t)(o0+oo)*Cin + c0+cc];
        }
#pragma unroll
        for (int r=0;r<16;r++){
            int l = tid + r*128;
            int cc = l>>7, tt = l&127;
            x_sm[cc][tt] = xb[(size_t)(c0+cc)*T_ + t0+tt];
        }
        __syncthreads();
#pragma unroll
        for (int cc=0;cc<16;cc++){
            float wr[8];
#pragma unroll
            for (int i=0;i<8;i++) wr[i]=w_sm[cc][wy*8+i];
#pragma unroll
            for (int j=0;j<8;j++){
                float xv = x_sm[cc][wx+16*j];
#pragma unroll
                for (int i=0;i<8;i++) acc[i][j] += wr[i]*xv;
            }
        }
        __syncthreads();
    }
#pragma unroll
    for (int i=0;i<8;i++){
        int o = o0 + wy*8 + i;
        float bv = bias[o];
        float* yrow = Y + (size_t)(b*Cout + o)*T_ + t0;
#pragma unroll
        for (int j=0;j<8;j++)
            yrow[wx+16*j] = alpha*(acc[i][j]+bv);
    }
}

/* ---------------- scores[bh,t,s] = sum_d q[bh*64+d,t] * k[bh*64+d,s] ---------------- */
__launch_bounds__(128)
__global__ void k_scores(const float* __restrict__ Q, const float* __restrict__ K,
                         float* __restrict__ P)
{
    const int s0 = blockIdx.x*128;
    const int t0 = blockIdx.y*64;
    const int bh = blockIdx.z;
    const float* qb = Q + (size_t)bh*64*T_;
    const float* kb = K + (size_t)bh*64*T_;
    __shared__ float q_sm[16][65];
    __shared__ float k_sm[16][128];
    const int tid = threadIdx.x;
    const int wx = tid & 15, wy = tid >> 4;
    float acc[8][8];
#pragma unroll
    for (int i=0;i<8;i++)
#pragma unroll
        for (int j=0;j<8;j++) acc[i][j]=0.f;

    for (int d0=0;d0<64;d0+=16){
#pragma unroll
        for (int r=0;r<8;r++){
            int l = tid + r*128;
            int cc = l>>6, oo = l&63;
            q_sm[cc][oo] = qb[(size_t)(d0+cc)*T_ + t0+oo];
        }
#pragma unroll
        for (int r=0;r<16;r++){
            int l = tid + r*128;
            int cc = l>>7, ss = l&127;
            k_sm[cc][ss] = kb[(size_t)(d0+cc)*T_ + s0+ss];
        }
        __syncthreads();
#pragma unroll
        for (int cc=0;cc<16;cc++){
            float wr[8];
#pragma unroll
            for (int i=0;i<8;i++) wr[i]=q_sm[cc][wy*8+i];
#pragma unroll
            for (int j=0;j<8;j++){
                float xv = k_sm[cc][wx+16*j];
#pragma unroll
                for (int i=0;i<8;i++) acc[i][j] += wr[i]*xv;
            }
        }
        __syncthreads();
    }
#pragma unroll
    for (int i=0;i<8;i++){
        float* prow = P + ((size_t)bh*T_ + t0+wy*8+i)*T_ + s0;
#pragma unroll
        for (int j=0;j<8;j++) prow[wx+16*j]=acc[i][j];
    }
}

/* ---------------- banded relative-K logits: scores[t, t+r-10] += q[t]·erk[r] ------- */
__global__ void k_relband(const float* __restrict__ Q, const float* __restrict__ erk,
                          float* __restrict__ P)
{
    const int bh = blockIdx.y;
    const int t = blockIdx.x*8 + (threadIdx.x>>5);
    const int lane = threadIdx.x & 31;
    const float* qb = Q + (size_t)bh*64*T_;
    float q0 = qb[(size_t)lane*T_ + t];
    float q1 = qb[(size_t)(lane+32)*T_ + t];
    float* prow = P + ((size_t)bh*T_ + t)*T_;
    for (int r=0;r<21;r++){
        float pd = q0*erk[r*64+lane] + q1*erk[r*64+32+lane];
#pragma unroll
        for (int o=16;o;o>>=1) pd += __shfl_xor_sync(0xffffffffu, pd, o);
        int s = t + r - WIN_;
        if (lane==0 && (unsigned)s < (unsigned)T_) prow[s] += pd;
    }
}

/* ---------------- row softmax with mask ---------------- */
__launch_bounds__(256)
__global__ void k_softmax(float* __restrict__ P, const float* __restrict__ mask)
{
    const int row = blockIdx.x;
    const int t  = row & (T_-1);
    const int bh = row >> 9;
    const int b  = bh >> 3;
    float* p = P + (size_t)row*T_;
    const float* mb = mask + b*T_;
    const int tid = threadIdx.x;
    const float mt = mb[t];
    float v0 = (mt*mb[tid]     != 0.f) ? p[tid]     : -1e4f;
    float v1 = (mt*mb[tid+256] != 0.f) ? p[tid+256] : -1e4f;
    __shared__ float red[256];
    red[tid] = fmaxf(v0,v1);
    __syncthreads();
    for (int o=128;o>0;o>>=1){
        if (tid<o) red[tid]=fmaxf(red[tid],red[tid+o]);
        __syncthreads();
    }
    float mx = red[0];
    __syncthreads();
    float e0 = expf(v0-mx), e1 = expf(v1-mx);
    red[tid]=e0+e1;
    __syncthreads();
    for (int o=128;o>0;o>>=1){
        if (tid<o) red[tid]+=red[tid+o];
        __syncthreads();
    }
    float inv = 1.f/red[0];
    p[tid]=e0*inv; p[tid+256]=e1*inv;
}

/* ---------------- ctx[bh*64+d, t] = sum_s v[d,s] p[t,s]  (+ banded rel-V) ---------- */
__launch_bounds__(128)
__global__ void k_ctx(const float* __restrict__ P, const float* __restrict__ V,
                      const float* __restrict__ erv, float* __restrict__ CTX)
{
    const int t0 = blockIdx.x*128;
    const int bh = blockIdx.y;
    const float* vb = V + (size_t)bh*64*T_;
    const float* pb = P + (size_t)bh*T_*T_;
    __shared__ float w_sm[16][65];
    __shared__ float x_sm[16][129];
    const int tid = threadIdx.x;
    const int wx = tid&15, wy = tid>>4;
    float acc[8][8];
#pragma unroll
    for (int i=0;i<8;i++)
#pragma unroll
        for (int j=0;j<8;j++) acc[i][j]=0.f;

    for (int s0=0;s0<T_;s0+=16){
#pragma unroll
        for (int r=0;r<8;r++){
            int l = tid + r*128;
            int oo = l>>4, cc = l&15;
            w_sm[cc][oo] = vb[(size_t)oo*T_ + s0+cc];
        }
#pragma unroll
        for (int r=0;r<16;r++){
            int l = tid + r*128;
            int tt = l>>4, ss = l&15;
            x_sm[ss][tt] = pb[(size_t)(t0+tt)*T_ + s0+ss];
        }
        __syncthreads();
#pragma unroll
        for (int cc=0;cc<16;cc++){
            float wr[8];
#pragma unroll
            for (int i=0;i<8;i++) wr[i]=w_sm[cc][wy*8+i];
#pragma unroll
            for (int j=0;j<8;j++){
                float xv = x_sm[cc][wx+16*j];
#pragma unroll
                for (int i=0;i<8;i++) acc[i][j]+=wr[i]*xv;
            }
        }
        __syncthreads();
    }
    /* banded rel-V: out[t,d] += sum_{|s-t|<=10} p[t,s] * erv[s-t+10, d] */
#pragma unroll
    for (int j=0;j<8;j++){
        int t = t0 + wx + 16*j;
        for (int r=0;r<21;r++){
            int s = t + r - WIN_;
            if ((unsigned)s < (unsigned)T_){
                float pv = pb[(size_t)t*T_ + s];
#pragma unroll
                for (int i=0;i<8;i++) acc[i][j] += pv*erv[r*64 + wy*8+i];
            }
        }
    }
#pragma unroll
    for (int i=0;i<8;i++){
        float* crow = CTX + (size_t)(bh*64 + wy*8+i)*T_ + t0;
#pragma unroll
        for (int j=0;j<8;j++) crow[wx+16*j]=acc[i][j];
    }
}

/* ---------------- K=3 'same' conv1d (GEMM over (c,k)) ---------------- */
__launch_bounds__(128)
__global__ void k_conv3(const float* __restrict__ X, const float* __restrict__ Wm,
                        const float* __restrict__ bias, const float* __restrict__ mask,
                        float* __restrict__ Y, int Cin, int Cout, int relu, int omask)
{
    const int t0 = blockIdx.x*128;
    const int o0 = blockIdx.y*64;
    const int b = blockIdx.z;
    __shared__ float w_sm[64][49];   /* [o][c*3+k] */
    __shared__ float x_sm[16][131];  /* col j <-> t0-1+j */
    const int tid = threadIdx.x;
    const int wx=tid&15, wy=tid>>4;
    float acc[8][8];
#pragma unroll
    for (int i=0;i<8;i++)
#pragma unroll
        for (int j=0;j<8;j++) acc[i][j]=0.f;

    const float* xb = X + (size_t)b*Cin*T_;
    const float* mb = mask + b*T_;
    for (int c0=0;c0<Cin;c0+=16){
#pragma unroll
        for (int r=0;r<24;r++){
            int l = tid + r*128;
            int oo = l/48, idx = l%48;
            w_sm[oo][idx] = Wm[(size_t)(o0+oo)*Cin*3 + (size_t)c0*3 + idx];
        }
#pragma unroll
        for (int r=0;r<17;r++){
            int l = tid + r*128;
            if (l < 2080){
                int cc = l/130, jj = l%130;
                int t = t0 + jj - 1;
                float v = 0.f;
                if (t>=0 && t<T_) v = xb[(size_t)(c0+cc)*T_ + t]*mb[t];
                x_sm[cc][jj] = v;
            }
        }
        __syncthreads();
#pragma unroll
        for (int cc=0;cc<16;cc++){
            float wr0[8],wr1[8],wr2[8];
#pragma unroll
            for (int i=0;i<8;i++){
                wr0[i]=w_sm[wy*8+i][cc*3+0];
                wr1[i]=w_sm[wy*8+i][cc*3+1];
                wr2[i]=w_sm[wy*8+i][cc*3+2];
            }
#pragma unroll
            for (int j=0;j<8;j++){
                int jj = wx + 16*j;
                float x0=x_sm[cc][jj], x1=x_sm[cc][jj+1], x2=x_sm[cc][jj+2];
#pragma unroll
                for (int i=0;i<8;i++)
                    acc[i][j] += wr0[i]*x0 + wr1[i]*x1 + wr2[i]*x2;
            }
        }
        __syncthreads();
    }
#pragma unroll
    for (int i=0;i<8;i++){
        int o = o0+wy*8+i;
        float bv = bias[o];
        float* yrow = Y + (size_t)(b*Cout + o)*T_ + t0;
#pragma unroll
        for (int j=0;j<8;j++){
            int tt = wx+16*j;
            float v = acc[i][j]+bv;
            if (relu) v = fmaxf(v, 0.f);
            if (omask) v *= mb[t0+tt];
            yrow[tt]=v;
        }
    }
}

/* ---------------- residual add + channel LayerNorm (in place on X) ---------------- */
__launch_bounds__(512)
__global__ void k_addln(float* __restrict__ X, const float* __restrict__ Yv,
                        const float* __restrict__ gamma, const float* __restrict__ beta)
{
    const int b = blockIdx.y;
    const int tl = threadIdx.x & 31;
    const int slot = threadIdx.x >> 5;     /* 0..15, each owns 32 channels */
    const int t = blockIdx.x*32 + tl;
    __shared__ float ssum[16][33];
    __shared__ float ssq[16][33];
    float vals[32];
    float s=0.f, q=0.f;
    size_t base = (size_t)b*C_*T_ + t;
#pragma unroll
    for (int u=0;u<32;u++){
        int c = slot*32+u;
        float v = X[base + (size_t)c*T_] + Yv[base + (size_t)c*T_];
        vals[u]=v; s+=v; q+=v*v;
    }
    ssum[slot][tl]=s; ssq[slot][tl]=q;
    __syncthreads();
    float m=0.f, vv=0.f;
#pragma unroll
    for (int k2=0;k2<16;k2++){ m+=ssum[k2][tl]; vv+=ssq[k2][tl]; }
    m *= (1.f/512.f);
    vv = vv*(1.f/512.f) - m*m;
    float r = rsqrtf(vv + 1e-5f);
#pragma unroll
    for (int u=0;u<32;u++){
        int c = slot*32+u;
        X[base + (size_t)c*T_] = (vals[u]-m)*r*gamma[c] + beta[c];
    }
}

/* ---------------- host orchestration ---------------- */
extern "C" void kernel_launch(void* const* d_in, const int* in_sizes, int n_in,
                              void* d_out, int out_size)
{
    (void)in_sizes; (void)n_in; (void)out_size;
    const float* x_in = (const float*)d_in[0];
    const float* mask = (const float*)d_in[1];
    const float* Wq  = (const float*)d_in[2];
    const float* bq  = (const float*)d_in[3];
    const float* Wk  = (const float*)d_in[4];
    const float* bk  = (const float*)d_in[5];
    const float* Wv  = (const float*)d_in[6];
    const float* bv  = (const float*)d_in[7];
    const float* Wo  = (const float*)d_in[8];
    const float* bo  = (const float*)d_in[9];
    const float* erk = (const float*)d_in[10];
    const float* erv = (const float*)d_in[11];
    const float* g1  = (const float*)d_in[12];
    const float* b1  = (const float*)d_in[13];
    const float* g2  = (const float*)d_in[14];
    const float* b2  = (const float*)d_in[15];
    const float* W1  = (const float*)d_in[16];
    const float* bf1 = (const float*)d_in[17];
    const float* W2  = (const float*)d_in[18];
    const float* bf2 = (const float*)d_in[19];

    float* pool = 0;
    cudaGetSymbolAddress((void**)&pool, g_pool);
    float* px = pool;
    float* pq = pool + (size_t)1*ELT_X;
    float* pk = pool + (size_t)2*ELT_X;
    float* pv = pool + (size_t)3*ELT_X;
    float* pc = pool + (size_t)4*ELT_X;
    float* py = pool + (size_t)5*ELT_X;
    float* ph = pool + (size_t)6*ELT_X;
    float* pp = pool + (size_t)6*ELT_X + ELT_H;

    k_maskmul<<<ELT_X/256,256>>>(x_in, mask, px);
    dim3 gP(T_/128, C_/64, B_);
    for (int L=0;L<6;L++){
        const float* wq = Wq + (size_t)L*C_*C_;
        const float* wk = Wk + (size_t)L*C_*C_;
        const float* wv = Wv + (size_t)L*C_*C_;
        const float* wo = Wo + (size_t)L*C_*C_;
        const float* w1 = W1 + (size_t)L*F_*C_*3;
        const float* w2 = W2 + (size_t)L*C_*F_*3;

        k_conv1x1<<<gP,128>>>(px, wq, bq + L*C_, pq, C_, C_, 0.125f);
        k_conv1x1<<<gP,128>>>(px, wk, bk + L*C_, pk, C_, C_, 1.f);
        k_conv1x1<<<gP,128>>>(px, wv, bv + L*C_, pv, C_, C_, 1.f);
        k_scores<<<dim3(T_/128, T_/64, B_*H_),128>>>(pq, pk, pp);
        k_relband<<<dim3(T_/8, B_*H_),256>>>(pq, erk + L*21*64, pp);
        k_softmax<<<B_*H_*T_,256>>>(pp, mask);
        k_ctx<<<dim3(T_/128, B_*H_),128>>>(pp, pv, erv + L*21*64, pc);
        k_conv1x1<<<gP,128>>>(pc, wo, bo + L*C_, py, C_, C_, 1.f);
        k_addln<<<dim3(T_/32,B_),512>>>(px, py, g1+L*C_, b1+L*C_);
        k_conv3<<<dim3(T_/128, F_/64, B_),128>>>(px, w1, bf1+L*F_, mask, ph, C_, F_, 1, 0);
        k_conv3<<<dim3(T_/128, C_/64, B_),128>>>(ph, w2, bf2+L*C_, mask, py, F_, C_, 0, 1);
        k_addln<<<dim3(T_/32,B_),512>>>(px, py, g2+L*C_, b2+L*C_);
    }
    k_maskmul<<<ELT_X/256,256>>>(px, mask, (float*)d_out);
}

// round 2
// speedup vs baseline: 1.7986x; 1.7986x over previous
#include <cuda_runtime.h>
#include <math.h>

#define B_ 8
#define T_ 512
#define C_ 512
#define H_ 8
#define F_ 2048
#define WIN_ 10

#define ELT_X (B_*C_*T_)
#define ELT_H (B_*F_*T_)
#define ELT_P (B_*H_*T_*T_)

__device__ float g_pool[(size_t)6*ELT_X + ELT_H + ELT_P];

__device__ __forceinline__ unsigned f2tf(float x){
    unsigned y; asm("cvt.rna.tf32.f32 %0, %1;" : "=r"(y) : "f"(x)); return y;
}
__device__ __forceinline__ void mma_tf32(float c[4], const unsigned a[4], const unsigned b[2]){
    asm("mma.sync.aligned.m16n8k8.row.col.f32.tf32.tf32.f32 "
        "{%0,%1,%2,%3}, {%4,%5,%6,%7}, {%8,%9}, {%0,%1,%2,%3};"
        : "+f"(c[0]), "+f"(c[1]), "+f"(c[2]), "+f"(c[3])
        : "r"(a[0]), "r"(a[1]), "r"(a[2]), "r"(a[3]), "r"(b[0]), "r"(b[1]));
}

/* ---------------- elementwise mask ---------------- */
__global__ void k_maskmul(const float* __restrict__ X, const float* __restrict__ mask,
                          float* __restrict__ Y)
{
    int i = blockIdx.x*256 + threadIdx.x;
    int t = i & (T_-1);
    int b = i / (C_*T_);
    Y[i] = X[i] * mask[b*T_ + t];
}

/* =========== tf32 MMA GEMM: Y[b,o,t] = alpha*(sum_c W[o,c] X[b,c,t] + bias[o]) ===== */
__launch_bounds__(256,1)
__global__ void g1x1(const float* __restrict__ X, const float* __restrict__ Wm,
                     const float* __restrict__ bias, float* __restrict__ Y,
                     int Cin, int Cout, float alpha)
{
    const int n0 = blockIdx.x*128;
    const int m0 = blockIdx.y*128;
    const int b  = blockIdx.z;
    const int tid = threadIdx.x;
    const int lane = tid & 31, wid = tid >> 5;
    const int gid = lane >> 2, tig = lane & 3;
    const int wm = wid & 1, wn = wid >> 1;

    __shared__ float smA[2][128][20];
    __shared__ float smB[2][16][136];

    const float* xb = X + (size_t)b*Cin*T_;
    const int rowA = tid >> 1, colA = (tid & 1)*8;
    const int rowB = tid >> 4, colB = (tid & 15)*8;

    float acc[4][4][4];
#pragma unroll
    for (int i=0;i<4;i++)
#pragma unroll
        for (int j=0;j<4;j++)
#pragma unroll
            for (int u=0;u<4;u++) acc[i][j][u]=0.f;

    const int KT = Cin/16;
    float pa[8], pb[8];

    /* prologue: tile 0 */
    {
        const float* ap = Wm + (size_t)(m0+rowA)*Cin + colA;
#pragma unroll
        for (int u=0;u<8;u++) pa[u]=ap[u];
        const float* bp = xb + (size_t)rowB*T_ + n0 + colB;
#pragma unroll
        for (int u=0;u<8;u++) pb[u]=bp[u];
#pragma unroll
        for (int u=0;u<8;u++) smA[0][rowA][colA+u]=__uint_as_float(f2tf(pa[u]));
#pragma unroll
        for (int u=0;u<8;u++) smB[0][rowB][colB+u]=__uint_as_float(f2tf(pb[u]));
    }
    __syncthreads();

    for (int kt=0; kt<KT; kt++){
        const int cur = kt & 1, nxt = cur ^ 1;
        const bool has = (kt+1 < KT);
        if (has){
            const int K0 = (kt+1)*16;
            const float* ap = Wm + (size_t)(m0+rowA)*Cin + K0 + colA;
#pragma unroll
            for (int u=0;u<8;u++) pa[u]=ap[u];
            const float* bp = xb + (size_t)(K0+rowB)*T_ + n0 + colB;
#pragma unroll
            for (int u=0;u<8;u++) pb[u]=bp[u];
        }
#pragma unroll
        for (int ks=0;ks<2;ks++){
            unsigned af[4][4], bf[4][2];
#pragma unroll
            for (int i=0;i<4;i++){
                int r = wm*64 + i*16 + gid;
                af[i][0]=__float_as_uint(smA[cur][r  ][ks*8+tig  ]);
                af[i][1]=__float_as_uint(smA[cur][r+8][ks*8+tig  ]);
                af[i][2]=__float_as_uint(smA[cur][r  ][ks*8+tig+4]);
                af[i][3]=__float_as_uint(smA[cur][r+8][ks*8+tig+4]);
            }
#pragma unroll
            for (int j=0;j<4;j++){
                int c = wn*32 + j*8 + gid;
                bf[j][0]=__float_as_uint(smB[cur][ks*8+tig  ][c]);
                bf[j][1]=__float_as_uint(smB[cur][ks*8+tig+4][c]);
            }
#pragma unroll
            for (int i=0;i<4;i++)
#pragma unroll
                for (int j=0;j<4;j++) mma_tf32(acc[i][j], af[i], bf[j]);
        }
        if (has){
#pragma unroll
            for (int u=0;u<8;u++) smA[nxt][rowA][colA+u]=__uint_as_float(f2tf(pa[u]));
#pragma unroll
            for (int u=0;u<8;u++) smB[nxt][rowB][colB+u]=__uint_as_float(f2tf(pb[u]));
        }
        __syncthreads();
    }

#pragma unroll
    for (int i=0;i<4;i++){
        int row = m0 + wm*64 + i*16 + gid;
        float bv0 = bias[row], bv8 = bias[row+8];
        float* y0 = Y + (size_t)(b*Cout + row)*T_;
        float* y8 = Y + (size_t)(b*Cout + row+8)*T_;
#pragma unroll
        for (int j=0;j<4;j++){
            int col = n0 + wn*32 + j*8 + tig*2;
            float2 v0 = make_float2(alpha*(acc[i][j][0]+bv0), alpha*(acc[i][j][1]+bv0));
            float2 v1 = make_float2(alpha*(acc[i][j][2]+bv8), alpha*(acc[i][j][3]+bv8));
            *(float2*)(y0+col)=v0;
            *(float2*)(y8+col)=v1;
        }
    }
}

/* =========== tf32 MMA GEMM for K=3 'same' conv (im2col over c*3+k) =========== */
__launch_bounds__(256,1)
__global__ void gconv3(const float* __restrict__ X, const float* __restrict__ Wm,
                       const float* __restrict__ bias, const float* __restrict__ mask,
                       float* __restrict__ Y, int Cin, int Cout, int relu, int omask)
{
    const int n0 = blockIdx.x*128;
    const int m0 = blockIdx.y*128;
    const int b  = blockIdx.z;
    const int tid = threadIdx.x;
    const int lane = tid & 31, wid = tid >> 5;
    const int gid = lane >> 2, tig = lane & 3;
    const int wm = wid & 1, wn = wid >> 1;

    __shared__ float smA[2][128][20];
    __shared__ float smB[2][16][136];

    const float* xb = X + (size_t)b*Cin*T_;
    const float* mb = mask + b*T_;
    const int Ktot = Cin*3;
    const int rowA = tid >> 1, colA = (tid & 1)*8;
    const int rowB = tid >> 4, colB = (tid & 15)*8;

    float acc[4][4][4];
#pragma unroll
    for (int i=0;i<4;i++)
#pragma unroll
        for (int j=0;j<4;j++)
#pragma unroll
            for (int u=0;u<4;u++) acc[i][j][u]=0.f;

    const int KT = Ktot/16;
    float pa[8], pb[8];

    /* tile-0 prologue */
    {
        const float* ap = Wm + (size_t)(m0+rowA)*Ktot + colA;
#pragma unroll
        for (int u=0;u<8;u++) pa[u]=ap[u];
        int kg = rowB;
        int cc = kg/3, kk = kg - cc*3;
        const float* xr = xb + (size_t)cc*T_;
        int tbase = n0 + colB + kk - 1;
#pragma unroll
        for (int u=0;u<8;u++){
            int t = tbase+u;
            pb[u] = ((unsigned)t < (unsigned)T_) ? xr[t]*mb[t] : 0.f;
        }
#pragma unroll
        for (int u=0;u<8;u++) smA[0][rowA][colA+u]=__uint_as_float(f2tf(pa[u]));
#pragma unroll
        for (int u=0;u<8;u++) smB[0][rowB][colB+u]=__uint_as_float(f2tf(pb[u]));
    }
    __syncthreads();

    for (int kt=0; kt<KT; kt++){
        const int cur = kt & 1, nxt = cur ^ 1;
        const bool has = (kt+1 < KT);
        if (has){
            const int K0 = (kt+1)*16;
            const float* ap = Wm + (size_t)(m0+rowA)*Ktot + K0 + colA;
#pragma unroll
            for (int u=0;u<8;u++) pa[u]=ap[u];
            int kg = K0 + rowB;
            int cc = kg/3, kk = kg - cc*3;
            const float* xr = xb + (size_t)cc*T_;
            int tbase = n0 + colB + kk - 1;
#pragma unroll
            for (int u=0;u<8;u++){
                int t = tbase+u;
                pb[u] = ((unsigned)t < (unsigned)T_) ? xr[t]*mb[t] : 0.f;
            }
        }
#pragma unroll
        for (int ks=0;ks<2;ks++){
            unsigned af[4][4], bf[4][2];
#pragma unroll
            for (int i=0;i<4;i++){
                int r = wm*64 + i*16 + gid;
                af[i][0]=__float_as_uint(smA[cur][r  ][ks*8+tig  ]);
                af[i][1]=__float_as_uint(smA[cur][r+8][ks*8+tig  ]);
                af[i][2]=__float_as_uint(smA[cur][r  ][ks*8+tig+4]);
                af[i][3]=__float_as_uint(smA[cur][r+8][ks*8+tig+4]);
            }
#pragma unroll
            for (int j=0;j<4;j++){
                int c = wn*32 + j*8 + gid;
                bf[j][0]=__float_as_uint(smB[cur][ks*8+tig  ][c]);
                bf[j][1]=__float_as_uint(smB[cur][ks*8+tig+4][c]);
            }
#pragma unroll
            for (int i=0;i<4;i++)
#pragma unroll
                for (int j=0;j<4;j++) mma_tf32(acc[i][j], af[i], bf[j]);
        }
        if (has){
#pragma unroll
            for (int u=0;u<8;u++) smA[nxt][rowA][colA+u]=__uint_as_float(f2tf(pa[u]));
#pragma unroll
            for (int u=0;u<8;u++) smB[nxt][rowB][colB+u]=__uint_as_float(f2tf(pb[u]));
        }
        __syncthreads();
    }

#pragma unroll
    for (int i=0;i<4;i++){
        int row = m0 + wm*64 + i*16 + gid;
        float bv0 = bias[row], bv8 = bias[row+8];
        float* y0 = Y + (size_t)(b*Cout + row)*T_;
        float* y8 = Y + (size_t)(b*Cout + row+8)*T_;
#pragma unroll
        for (int j=0;j<4;j++){
            int col = n0 + wn*32 + j*8 + tig*2;
            float v00 = acc[i][j][0]+bv0, v01 = acc[i][j][1]+bv0;
            float v10 = acc[i][j][2]+bv8, v11 = acc[i][j][3]+bv8;
            if (relu){ v00=fmaxf(v00,0.f); v01=fmaxf(v01,0.f); v10=fmaxf(v10,0.f); v11=fmaxf(v11,0.f); }
            if (omask){
                float mA = mb[col], mBv = mb[col+1];
                v00*=mA; v01*=mBv; v10*=mA; v11*=mBv;
            }
            *(float2*)(y0+col)=make_float2(v00,v01);
            *(float2*)(y8+col)=make_float2(v10,v11);
        }
    }
}

/* ---------------- scores[bh,t,s] = sum_d q[bh*64+d,t] * k[bh*64+d,s] ---------------- */
__launch_bounds__(128)
__global__ void k_scores(const float* __restrict__ Q, const float* __restrict__ K,
                         float* __restrict__ P)
{
    const int s0 = blockIdx.x*128;
    const int t0 = blockIdx.y*64;
    const int bh = blockIdx.z;
    const float* qb = Q + (size_t)bh*64*T_;
    const float* kb = K + (size_t)bh*64*T_;
    __shared__ float q_sm[16][65];
    __shared__ float k_sm[16][128];
    const int tid = threadIdx.x;
    const int wx = tid & 15, wy = tid >> 4;
    float acc[8][8];
#pragma unroll
    for (int i=0;i<8;i++)
#pragma unroll
        for (int j=0;j<8;j++) acc[i][j]=0.f;

    for (int d0=0;d0<64;d0+=16){
#pragma unroll
        for (int r=0;r<8;r++){
            int l = tid + r*128;
            int cc = l>>6, oo = l&63;
            q_sm[cc][oo] = qb[(size_t)(d0+cc)*T_ + t0+oo];
        }
#pragma unroll
        for (int r=0;r<16;r++){
            int l = tid + r*128;
            int cc = l>>7, ss = l&127;
            k_sm[cc][ss] = kb[(size_t)(d0+cc)*T_ + s0+ss];
        }
        __syncthreads();
#pragma unroll
        for (int cc=0;cc<16;cc++){
            float wr[8];
#pragma unroll
            for (int i=0;i<8;i++) wr[i]=q_sm[cc][wy*8+i];
#pragma unroll
            for (int j=0;j<8;j++){
                float xv = k_sm[cc][wx+16*j];
#pragma unroll
                for (int i=0;i<8;i++) acc[i][j] += wr[i]*xv;
            }
        }
        __syncthreads();
    }
#pragma unroll
    for (int i=0;i<8;i++){
        float* prow = P + ((size_t)bh*T_ + t0+wy*8+i)*T_ + s0;
#pragma unroll
        for (int j=0;j<8;j++) prow[wx+16*j]=acc[i][j];
    }
}

/* ---------------- banded relative-K logits ---------------- */
__global__ void k_relband(const float* __restrict__ Q, const float* __restrict__ erk,
                          float* __restrict__ P)
{
    const int bh = blockIdx.y;
    const int t = blockIdx.x*8 + (threadIdx.x>>5);
    const int lane = threadIdx.x & 31;
    const float* qb = Q + (size_t)bh*64*T_;
    float q0 = qb[(size_t)lane*T_ + t];
    float q1 = qb[(size_t)(lane+32)*T_ + t];
    float* prow = P + ((size_t)bh*T_ + t)*T_;
    for (int r=0;r<21;r++){
        float pd = q0*erk[r*64+lane] + q1*erk[r*64+32+lane];
#pragma unroll
        for (int o=16;o;o>>=1) pd += __shfl_xor_sync(0xffffffffu, pd, o);
        int s = t + r - WIN_;
        if (lane==0 && (unsigned)s < (unsigned)T_) prow[s] += pd;
    }
}

/* ---------------- row softmax with mask ---------------- */
__launch_bounds__(256)
__global__ void k_softmax(float* __restrict__ P, const float* __restrict__ mask)
{
    const int row = blockIdx.x;
    const int t  = row & (T_-1);
    const int bh = row >> 9;
    const int b  = bh >> 3;
    float* p = P + (size_t)row*T_;
    const float* mb = mask + b*T_;
    const int tid = threadIdx.x;
    const float mt = mb[t];
    float v0 = (mt*mb[tid]     != 0.f) ? p[tid]     : -1e4f;
    float v1 = (mt*mb[tid+256] != 0.f) ? p[tid+256] : -1e4f;
    __shared__ float red[256];
    red[tid] = fmaxf(v0,v1);
    __syncthreads();
    for (int o=128;o>0;o>>=1){
        if (tid<o) red[tid]=fmaxf(red[tid],red[tid+o]);
        __syncthreads();
    }
    float mx = red[0];
    __syncthreads();
    float e0 = expf(v0-mx), e1 = expf(v1-mx);
    red[tid]=e0+e1;
    __syncthreads();
    for (int o=128;o>0;o>>=1){
        if (tid<o) red[tid]+=red[tid+o];
        __syncthreads();
    }
    float inv = 1.f/red[0];
    p[tid]=e0*inv; p[tid+256]=e1*inv;
}

/* ---------------- ctx = p @ v (+ banded rel-V) ---------------- */
__launch_bounds__(128)
__global__ void k_ctx(const float* __restrict__ P, const float* __restrict__ V,
                      const float* __restrict__ erv, float* __restrict__ CTX)
{
    const int t0 = blockIdx.x*128;
    const int bh = blockIdx.y;
    const float* vb = V + (size_t)bh*64*T_;
    const float* pb = P + (size_t)bh*T_*T_;
    __shared__ float w_sm[16][65];
    __shared__ float x_sm[16][129];
    const int tid = threadIdx.x;
    const int wx = tid&15, wy = tid>>4;
    float acc[8][8];
#pragma unroll
    for (int i=0;i<8;i++)
#pragma unroll
        for (int j=0;j<8;j++) acc[i][j]=0.f;

    for (int s0=0;s0<T_;s0+=16){
#pragma unroll
        for (int r=0;r<8;r++){
            int l = tid + r*128;
            int oo = l>>4, cc = l&15;
            w_sm[cc][oo] = vb[(size_t)oo*T_ + s0+cc];
        }
#pragma unroll
        for (int r=0;r<16;r++){
            int l = tid + r*128;
            int tt = l>>4, ss = l&15;
            x_sm[ss][tt] = pb[(size_t)(t0+tt)*T_ + s0+ss];
        }
        __syncthreads();
#pragma unroll
        for (int cc=0;cc<16;cc++){
            float wr[8];
#pragma unroll
            for (int i=0;i<8;i++) wr[i]=w_sm[cc][wy*8+i];
#pragma unroll
            for (int j=0;j<8;j++){
                float xv = x_sm[cc][wx+16*j];
#pragma unroll
                for (int i=0;i<8;i++) acc[i][j]+=wr[i]*xv;
            }
        }
        __syncthreads();
    }
#pragma unroll
    for (int j=0;j<8;j++){
        int t = t0 + wx + 16*j;
        for (int r=0;r<21;r++){
            int s = t + r - WIN_;
            if ((unsigned)s < (unsigned)T_){
                float pv = pb[(size_t)t*T_ + s];
#pragma unroll
                for (int i=0;i<8;i++) acc[i][j] += pv*erv[r*64 + wy*8+i];
            }
        }
    }
#pragma unroll
    for (int i=0;i<8;i++){
        float* crow = CTX + (size_t)(bh*64 + wy*8+i)*T_ + t0;
#pragma unroll
        for (int j=0;j<8;j++) crow[wx+16*j]=acc[i][j];
    }
}

/* ---------------- residual add + channel LayerNorm (in place on X) ---------------- */
__launch_bounds__(512)
__global__ void k_addln(float* __restrict__ X, const float* __restrict__ Yv,
                        const float* __restrict__ gamma, const float* __restrict__ beta)
{
    const int b = blockIdx.y;
    const int tl = threadIdx.x & 31;
    const int slot = threadIdx.x >> 5;
    const int t = blockIdx.x*32 + tl;
    __shared__ float ssum[16][33];
    __shared__ float ssq[16][33];
    float vals[32];
    float s=0.f, q=0.f;
    size_t base = (size_t)b*C_*T_ + t;
#pragma unroll
    for (int u=0;u<32;u++){
        int c = slot*32+u;
        float v = X[base + (size_t)c*T_] + Yv[base + (size_t)c*T_];
        vals[u]=v; s+=v; q+=v*v;
    }
    ssum[slot][tl]=s; ssq[slot][tl]=q;
    __syncthreads();
    float m=0.f, vv=0.f;
#pragma unroll
    for (int k2=0;k2<16;k2++){ m+=ssum[k2][tl]; vv+=ssq[k2][tl]; }
    m *= (1.f/512.f);
    vv = vv*(1.f/512.f) - m*m;
    float r = rsqrtf(vv + 1e-5f);
#pragma unroll
    for (int u=0;u<32;u++){
        int c = slot*32+u;
        X[base + (size_t)c*T_] = (vals[u]-m)*r*gamma[c] + beta[c];
    }
}

/* ---------------- host orchestration ---------------- */
extern "C" void kernel_launch(void* const* d_in, const int* in_sizes, int n_in,
                              void* d_out, int out_size)
{
    (void)in_sizes; (void)n_in; (void)out_size;
    const float* x_in = (const float*)d_in[0];
    const float* mask = (const float*)d_in[1];
    const float* Wq  = (const float*)d_in[2];
    const float* bq  = (const float*)d_in[3];
    const float* Wk  = (const float*)d_in[4];
    const float* bk  = (const float*)d_in[5];
    const float* Wv  = (const float*)d_in[6];
    const float* bv  = (const float*)d_in[7];
    const float* Wo  = (const float*)d_in[8];
    const float* bo  = (const float*)d_in[9];
    const float* erk = (const float*)d_in[10];
    const float* erv = (const float*)d_in[11];
    const float* g1  = (const float*)d_in[12];
    const float* b1  = (const float*)d_in[13];
    const float* g2  = (const float*)d_in[14];
    const float* b2  = (const float*)d_in[15];
    const float* W1  = (const float*)d_in[16];
    const float* bf1 = (const float*)d_in[17];
    const float* W2  = (const float*)d_in[18];
    const float* bf2 = (const float*)d_in[19];

    float* pool = 0;
    cudaGetSymbolAddress((void**)&pool, g_pool);
    float* px = pool;
    float* pq = pool + (size_t)1*ELT_X;
    float* pk = pool + (size_t)2*ELT_X;
    float* pv = pool + (size_t)3*ELT_X;
    float* pc = pool + (size_t)4*ELT_X;
    float* py = pool + (size_t)5*ELT_X;
    float* ph = pool + (size_t)6*ELT_X;
    float* pp = pool + (size_t)6*ELT_X + ELT_H;

    k_maskmul<<<ELT_X/256,256>>>(x_in, mask, px);
    dim3 gP(T_/128, C_/128, B_);
    for (int L=0;L<6;L++){
        const float* wq = Wq + (size_t)L*C_*C_;
        const float* wk = Wk + (size_t)L*C_*C_;
        const float* wv = Wv + (size_t)L*C_*C_;
        const float* wo = Wo + (size_t)L*C_*C_;
        const float* w1 = W1 + (size_t)L*F_*C_*3;
        const float* w2 = W2 + (size_t)L*C_*F_*3;

        g1x1<<<gP,256>>>(px, wq, bq + L*C_, pq, C_, C_, 0.125f);
        g1x1<<<gP,256>>>(px, wk, bk + L*C_, pk, C_, C_, 1.f);
        g1x1<<<gP,256>>>(px, wv, bv + L*C_, pv, C_, C_, 1.f);
        k_scores<<<dim3(T_/128, T_/64, B_*H_),128>>>(pq, pk, pp);
        k_relband<<<dim3(T_/8, B_*H_),256>>>(pq, erk + L*21*64, pp);
        k_softmax<<<B_*H_*T_,256>>>(pp, mask);
        k_ctx<<<dim3(T_/128, B_*H_),128>>>(pp, pv, erv + L*21*64, pc);
        g1x1<<<gP,256>>>(pc, wo, bo + L*C_, py, C_, C_, 1.f);
        k_addln<<<dim3(T_/32,B_),512>>>(px, py, g1+L*C_, b1+L*C_);
        gconv3<<<dim3(T_/128, F_/128, B_),256>>>(px, w1, bf1+L*F_, mask, ph, C_, F_, 1, 0);
        gconv3<<<dim3(T_/128, C_/128, B_),256>>>(ph, w2, bf2+L*C_, mask, py, F_, C_, 0, 1);
        k_addln<<<dim3(T_/32,B_),512>>>(px, py, g2+L*C_, b2+L*C_);
    }
    k_maskmul<<<ELT_X/256,256>>>(px, mask, (float*)d_out);
}

// round 3
// speedup vs baseline: 2.0170x; 1.1215x over previous
#include <cuda_runtime.h>
#include <math.h>

#define B_ 8
#define T_ 512
#define C_ 512
#define H_ 8
#define F_ 2048
#define WIN_ 10
#define TP_ 516   /* padded row: [pad1][512][pad3], 16B-aligned stride */

#define ELT_X (B_*C_*T_)
#define ELT_H (B_*F_*T_)
#define ELT_P (B_*H_*T_*T_)
#define ELT_XP (B_*C_*TP_)
#define ELT_HP (B_*F_*TP_)

__device__ float g_pool[(size_t)6*ELT_X + ELT_P + ELT_XP + ELT_HP];

__device__ __forceinline__ unsigned f2tf(float x){
    unsigned y; asm("cvt.rna.tf32.f32 %0, %1;" : "=r"(y) : "f"(x)); return y;
}
__device__ __forceinline__ void mma_tf32(float c[4], const unsigned a[4], const unsigned b[2]){
    asm("mma.sync.aligned.m16n8k8.row.col.f32.tf32.tf32.f32 "
        "{%0,%1,%2,%3}, {%4,%5,%6,%7}, {%8,%9}, {%0,%1,%2,%3};"
        : "+f"(c[0]), "+f"(c[1]), "+f"(c[2]), "+f"(c[3])
        : "r"(a[0]), "r"(a[1]), "r"(a[2]), "r"(a[3]), "r"(b[0]), "r"(b[1]));
}

/* ---------------- elementwise mask ---------------- */
__global__ void k_maskmul(const float* __restrict__ X, const float* __restrict__ mask,
                          float* __restrict__ Y)
{
    int i = blockIdx.x*256 + threadIdx.x;
    int t = i & (T_-1);
    int b = i / (C_*T_);
    Y[i] = X[i] * mask[b*T_ + t];
}

/* ---------------- pad+mask: px -> pxp ([C][TP_] with col offset 1) ---------------- */
__global__ void k_pad(const float* __restrict__ X, const float* __restrict__ mask,
                      float* __restrict__ Xp)
{
    int i = blockIdx.x*256 + threadIdx.x;
    int t = i & (T_-1);
    int c = (i >> 9) & (C_-1);
    int b = i >> 18;
    Xp[((size_t)(b*C_+c))*TP_ + t + 1] = X[i]*mask[b*T_ + t];
}

/* ---------------- zero pad borders of pxp and php (once per launch) ------------- */
__global__ void k_zb(float* __restrict__ Xp, float* __restrict__ Hp)
{
    int r = blockIdx.x*256 + threadIdx.x;   /* r < B_*C_ + B_*F_ = 20480 */
    float* base = (r < B_*C_) ? (Xp + (size_t)r*TP_) : (Hp + (size_t)(r - B_*C_)*TP_);
    base[0]=0.f; base[513]=0.f; base[514]=0.f; base[515]=0.f;
}

/* =========== tf32 MMA GEMM: Y[b,o,t] = alpha*(sum_c W[o,c] X[b,c,t] + bias[o]) ===== */
__launch_bounds__(256,2)
__global__ void g1x1(const float* __restrict__ X, const float* __restrict__ Wm,
                     const float* __restrict__ bias, float* __restrict__ Y,
                     int Cin, int Cout, float alpha)
{
    const int n0 = blockIdx.x*128;
    const int m0 = blockIdx.y*128;
    const int b  = blockIdx.z;
    const int tid = threadIdx.x;
    const int lane = tid & 31, wid = tid >> 5;
    const int gid = lane >> 2, tig = lane & 3;
    const int wm = wid & 1, wn = wid >> 1;

    __shared__ float smA[2][128][20];
    __shared__ float smB[2][16][136];

    const float* xb = X + (size_t)b*Cin*T_;
    const int rowA = tid >> 1, colA = (tid & 1)*8;
    const int rowB = tid >> 4, colB = (tid & 15)*8;

    float acc[4][4][4];
#pragma unroll
    for (int i=0;i<4;i++)
#pragma unroll
        for (int j=0;j<4;j++)
#pragma unroll
            for (int u=0;u<4;u++) acc[i][j][u]=0.f;

    const int KT = Cin/16;
    float pa[8], pb[8];
    {
        const float* ap = Wm + (size_t)(m0+rowA)*Cin + colA;
#pragma unroll
        for (int u=0;u<8;u++) pa[u]=ap[u];
        const float* bp = xb + (size_t)rowB*T_ + n0 + colB;
#pragma unroll
        for (int u=0;u<8;u++) pb[u]=bp[u];
#pragma unroll
        for (int u=0;u<8;u++) smA[0][rowA][colA+u]=__uint_as_float(f2tf(pa[u]));
#pragma unroll
        for (int u=0;u<8;u++) smB[0][rowB][colB+u]=__uint_as_float(f2tf(pb[u]));
    }
    __syncthreads();

    for (int kt=0; kt<KT; kt++){
        const int cur = kt & 1, nxt = cur ^ 1;
        const bool has = (kt+1 < KT);
        if (has){
            const int K0 = (kt+1)*16;
            const float* ap = Wm + (size_t)(m0+rowA)*Cin + K0 + colA;
#pragma unroll
            for (int u=0;u<8;u++) pa[u]=ap[u];
            const float* bp = xb + (size_t)(K0+rowB)*T_ + n0 + colB;
#pragma unroll
            for (int u=0;u<8;u++) pb[u]=bp[u];
        }
#pragma unroll
        for (int ks=0;ks<2;ks++){
            unsigned af[4][4], bf[4][2];
#pragma unroll
            for (int i=0;i<4;i++){
                int r = wm*64 + i*16 + gid;
                af[i][0]=__float_as_uint(smA[cur][r  ][ks*8+tig  ]);
                af[i][1]=__float_as_uint(smA[cur][r+8][ks*8+tig  ]);
                af[i][2]=__float_as_uint(smA[cur][r  ][ks*8+tig+4]);
                af[i][3]=__float_as_uint(smA[cur][r+8][ks*8+tig+4]);
            }
#pragma unroll
            for (int j=0;j<4;j++){
                int c = wn*32 + j*8 + gid;
                bf[j][0]=__float_as_uint(smB[cur][ks*8+tig  ][c]);
                bf[j][1]=__float_as_uint(smB[cur][ks*8+tig+4][c]);
            }
#pragma unroll
            for (int i=0;i<4;i++)
#pragma unroll
                for (int j=0;j<4;j++) mma_tf32(acc[i][j], af[i], bf[j]);
        }
        if (has){
#pragma unroll
            for (int u=0;u<8;u++) smA[nxt][rowA][colA+u]=__uint_as_float(f2tf(pa[u]));
#pragma unroll
            for (int u=0;u<8;u++) smB[nxt][rowB][colB+u]=__uint_as_float(f2tf(pb[u]));
        }
        __syncthreads();
    }

#pragma unroll
    for (int i=0;i<4;i++){
        int row = m0 + wm*64 + i*16 + gid;
        float bv0 = bias[row], bv8 = bias[row+8];
        float* y0 = Y + (size_t)(b*Cout + row)*T_;
        float* y8 = Y + (size_t)(b*Cout + row+8)*T_;
#pragma unroll
        for (int j=0;j<4;j++){
            int col = n0 + wn*32 + j*8 + tig*2;
            *(float2*)(y0+col)=make_float2(alpha*(acc[i][j][0]+bv0), alpha*(acc[i][j][1]+bv0));
            *(float2*)(y8+col)=make_float2(alpha*(acc[i][j][2]+bv8), alpha*(acc[i][j][3]+bv8));
        }
    }
}

/* =========== fused Q/K/V projection: grid.y selects matrix (12 = 3 x 4 tiles) ===== */
__launch_bounds__(256,2)
__global__ void g_qkv(const float* __restrict__ X,
                      const float* __restrict__ Wq, const float* __restrict__ Wk, const float* __restrict__ Wv,
                      const float* __restrict__ bq, const float* __restrict__ bk, const float* __restrict__ bv,
                      float* __restrict__ Yq, float* __restrict__ Yk, float* __restrict__ Yv)
{
    const int n0 = blockIdx.x*128;
    const int mi = blockIdx.y;
    const int sel = mi >> 2;
    const int m0 = (mi & 3)*128;
    const int b  = blockIdx.z;
    const float* Wm  = (sel==0)?Wq:(sel==1)?Wk:Wv;
    const float* bias= (sel==0)?bq:(sel==1)?bk:bv;
    float* Y         = (sel==0)?Yq:(sel==1)?Yk:Yv;
    const float alpha= (sel==0)?0.125f:1.f;

    const int tid = threadIdx.x;
    const int lane = tid & 31, wid = tid >> 5;
    const int gid = lane >> 2, tig = lane & 3;
    const int wm = wid & 1, wn = wid >> 1;

    __shared__ float smA[2][128][20];
    __shared__ float smB[2][16][136];

    const float* xb = X + (size_t)b*C_*T_;
    const int rowA = tid >> 1, colA = (tid & 1)*8;
    const int rowB = tid >> 4, colB = (tid & 15)*8;

    float acc[4][4][4];
#pragma unroll
    for (int i=0;i<4;i++)
#pragma unroll
        for (int j=0;j<4;j++)
#pragma unroll
            for (int u=0;u<4;u++) acc[i][j][u]=0.f;

    const int KT = C_/16;
    float pa[8], pb[8];
    {
        const float* ap = Wm + (size_t)(m0+rowA)*C_ + colA;
#pragma unroll
        for (int u=0;u<8;u++) pa[u]=ap[u];
        const float* bp = xb + (size_t)rowB*T_ + n0 + colB;
#pragma unroll
        for (int u=0;u<8;u++) pb[u]=bp[u];
#pragma unroll
        for (int u=0;u<8;u++) smA[0][rowA][colA+u]=__uint_as_float(f2tf(pa[u]));
#pragma unroll
        for (int u=0;u<8;u++) smB[0][rowB][colB+u]=__uint_as_float(f2tf(pb[u]));
    }
    __syncthreads();

    for (int kt=0; kt<KT; kt++){
        const int cur = kt & 1, nxt = cur ^ 1;
        const bool has = (kt+1 < KT);
        if (has){
            const int K0 = (kt+1)*16;
            const float* ap = Wm + (size_t)(m0+rowA)*C_ + K0 + colA;
#pragma unroll
            for (int u=0;u<8;u++) pa[u]=ap[u];
            const float* bp = xb + (size_t)(K0+rowB)*T_ + n0 + colB;
#pragma unroll
            for (int u=0;u<8;u++) pb[u]=bp[u];
        }
#pragma unroll
        for (int ks=0;ks<2;ks++){
            unsigned af[4][4], bf[4][2];
#pragma unroll
            for (int i=0;i<4;i++){
                int r = wm*64 + i*16 + gid;
                af[i][0]=__float_as_uint(smA[cur][r  ][ks*8+tig  ]);
                af[i][1]=__float_as_uint(smA[cur][r+8][ks*8+tig  ]);
                af[i][2]=__float_as_uint(smA[cur][r  ][ks*8+tig+4]);
                af[i][3]=__float_as_uint(smA[cur][r+8][ks*8+tig+4]);
            }
#pragma unroll
            for (int j=0;j<4;j++){
                int c = wn*32 + j*8 + gid;
                bf[j][0]=__float_as_uint(smB[cur][ks*8+tig  ][c]);
                bf[j][1]=__float_as_uint(smB[cur][ks*8+tig+4][c]);
            }
#pragma unroll
            for (int i=0;i<4;i++)
#pragma unroll
                for (int j=0;j<4;j++) mma_tf32(acc[i][j], af[i], bf[j]);
        }
        if (has){
#pragma unroll
            for (int u=0;u<8;u++) smA[nxt][rowA][colA+u]=__uint_as_float(f2tf(pa[u]));
#pragma unroll
            for (int u=0;u<8;u++) smB[nxt][rowB][colB+u]=__uint_as_float(f2tf(pb[u]));
        }
        __syncthreads();
    }

#pragma unroll
    for (int i=0;i<4;i++){
        int row = m0 + wm*64 + i*16 + gid;
        float bv0 = bias[row], bv8 = bias[row+8];
        float* y0 = Y + (size_t)(b*C_ + row)*T_;
        float* y8 = Y + (size_t)(b*C_ + row+8)*T_;
#pragma unroll
        for (int j=0;j<4;j++){
            int col = n0 + wn*32 + j*8 + tig*2;
            *(float2*)(y0+col)=make_float2(alpha*(acc[i][j][0]+bv0), alpha*(acc[i][j][1]+bv0));
            *(float2*)(y8+col)=make_float2(alpha*(acc[i][j][2]+bv8), alpha*(acc[i][j][3]+bv8));
        }
    }
}

/* =========== tf32 MMA K=3 conv GEMM on padded pre-masked input ===============
   mode 0: epilogue relu(acc+bias)*mask -> padded output (stride TP_, offset +1)
   mode 1: raw partial store to Y + part*ELT_X (split-K), no bias             */
__launch_bounds__(256,2)
__global__ void gconv3p(const float* __restrict__ Xp, const float* __restrict__ Wm,
                        const float* __restrict__ bias, const float* __restrict__ mask,
                        float* __restrict__ Y, int Cin, int Cout,
                        int mode, int ktiles)
{
    const int n0 = blockIdx.x*128;
    const int m0 = blockIdx.y*128;
    const int bz = blockIdx.z;
    const int b    = (mode==1) ? (bz & 7) : bz;
    const int part = (mode==1) ? (bz >> 3) : 0;
    const int kOff = part*(ktiles*16);

    const int tid = threadIdx.x;
    const int lane = tid & 31, wid = tid >> 5;
    const int gid = lane >> 2, tig = lane & 3;
    const int wm = wid & 1, wn = wid >> 1;

    __shared__ float smA[2][128][20];
    __shared__ float smB[2][16][136];

    const float* xpb = Xp + (size_t)b*Cin*TP_;
    const int Ktot = Cin*3;
    const int rowA = tid >> 1, colA = (tid & 1)*8;
    const int rowB = tid >> 4, colB = (tid & 15)*8;

    float acc[4][4][4];
#pragma unroll
    for (int i=0;i<4;i++)
#pragma unroll
        for (int j=0;j<4;j++)
#pragma unroll
            for (int u=0;u<4;u++) acc[i][j][u]=0.f;

    float pa[8], pb[8];
    {
        const float* ap = Wm + (size_t)(m0+rowA)*Ktot + kOff + colA;
#pragma unroll
        for (int u=0;u<8;u++) pa[u]=ap[u];
        int kg = kOff + rowB;
        int cc = kg/3, kk = kg - cc*3;
        const float* bp = xpb + (size_t)cc*TP_ + n0 + colB + kk;
#pragma unroll
        for (int u=0;u<8;u++) pb[u]=bp[u];
#pragma unroll
        for (int u=0;u<8;u++) smA[0][rowA][colA+u]=__uint_as_float(f2tf(pa[u]));
#pragma unroll
        for (int u=0;u<8;u++) smB[0][rowB][colB+u]=__uint_as_float(f2tf(pb[u]));
    }
    __syncthreads();

    for (int kt=0; kt<ktiles; kt++){
        const int cur = kt & 1, nxt = cur ^ 1;
        const bool has = (kt+1 < ktiles);
        if (has){
            const int K0 = kOff + (kt+1)*16;
            const float* ap = Wm + (size_t)(m0+rowA)*Ktot + K0 + colA;
#pragma unroll
            for (int u=0;u<8;u++) pa[u]=ap[u];
            int kg = K0 + rowB;
            int cc = kg/3, kk = kg - cc*3;
            const float* bp = xpb + (size_t)cc*TP_ + n0 + colB + kk;
#pragma unroll
            for (int u=0;u<8;u++) pb[u]=bp[u];
        }
#pragma unroll
        for (int ks=0;ks<2;ks++){
            unsigned af[4][4], bf[4][2];
#pragma unroll
            for (int i=0;i<4;i++){
                int r = wm*64 + i*16 + gid;
                af[i][0]=__float_as_uint(smA[cur][r  ][ks*8+tig  ]);
                af[i][1]=__float_as_uint(smA[cur][r+8][ks*8+tig  ]);
                af[i][2]=__float_as_uint(smA[cur][r  ][ks*8+tig+4]);
                af[i][3]=__float_as_uint(smA[cur][r+8][ks*8+tig+4]);
            }
#pragma unroll
            for (int j=0;j<4;j++){
                int c = wn*32 + j*8 + gid;
                bf[j][0]=__float_as_uint(smB[cur][ks*8+tig  ][c]);
                bf[j][1]=__float_as_uint(smB[cur][ks*8+tig+4][c]);
            }
#pragma unroll
            for (int i=0;i<4;i++)
#pragma unroll
                for (int j=0;j<4;j++) mma_tf32(acc[i][j], af[i], bf[j]);
        }
        if (has){
#pragma unroll
            for (int u=0;u<8;u++) smA[nxt][rowA][colA+u]=__uint_as_float(f2tf(pa[u]));
#pragma unroll
            for (int u=0;u<8;u++) smB[nxt][rowB][colB+u]=__uint_as_float(f2tf(pb[u]));
        }
        __syncthreads();
    }

    if (mode==0){
        const float* mb = mask + b*T_;
#pragma unroll
        for (int i=0;i<4;i++){
            int row = m0 + wm*64 + i*16 + gid;
            float bv0 = bias[row], bv8 = bias[row+8];
            float* y0 = Y + (size_t)(b*Cout + row)*TP_ + 1;
            float* y8 = Y + (size_t)(b*Cout + row+8)*TP_ + 1;
#pragma unroll
            for (int j=0;j<4;j++){
                int col = n0 + wn*32 + j*8 + tig*2;
                float m0v = mb[col], m1v = mb[col+1];
                y0[col]   = fmaxf(acc[i][j][0]+bv0, 0.f)*m0v;
                y0[col+1] = fmaxf(acc[i][j][1]+bv0, 0.f)*m1v;
                y8[col]   = fmaxf(acc[i][j][2]+bv8, 0.f)*m0v;
                y8[col+1] = fmaxf(acc[i][j][3]+bv8, 0.f)*m1v;
            }
        }
    } else {
#pragma unroll
        for (int i=0;i<4;i++){
            int row = m0 + wm*64 + i*16 + gid;
            float* y0 = Y + (size_t)part*ELT_X + (size_t)(b*Cout + row)*T_;
            float* y8 = Y + (size_t)part*ELT_X + (size_t)(b*Cout + row+8)*T_;
#pragma unroll
            for (int j=0;j<4;j++){
                int col = n0 + wn*32 + j*8 + tig*2;
                *(float2*)(y0+col)=make_float2(acc[i][j][0], acc[i][j][1]);
                *(float2*)(y8+col)=make_float2(acc[i][j][2], acc[i][j][3]);
            }
        }
    }
}

/* ---------------- split-K reduce + bias + mask ---------------- */
__global__ void k_red(const float* __restrict__ P0, const float* __restrict__ bias,
                      const float* __restrict__ mask, float* __restrict__ Y)
{
    int i = blockIdx.x*256 + threadIdx.x;
    int t = i & (T_-1);
    int o = (i >> 9) & (C_-1);
    int b = i >> 18;
    Y[i] = (P0[i] + P0[(size_t)ELT_X + i] + bias[o]) * mask[b*T_ + t];
}

/* ---------------- scores ---------------- */
__launch_bounds__(128)
__global__ void k_scores(const float* __restrict__ Q, const float* __restrict__ K,
                         float* __restrict__ P)
{
    const int s0 = blockIdx.x*128;
    const int t0 = blockIdx.y*64;
    const int bh = blockIdx.z;
    const float* qb = Q + (size_t)bh*64*T_;
    const float* kb = K + (size_t)bh*64*T_;
    __shared__ float q_sm[16][65];
    __shared__ float k_sm[16][128];
    const int tid = threadIdx.x;
    const int wx = tid & 15, wy = tid >> 4;
    float acc[8][8];
#pragma unroll
    for (int i=0;i<8;i++)
#pragma unroll
        for (int j=0;j<8;j++) acc[i][j]=0.f;

    for (int d0=0;d0<64;d0+=16){
#pragma unroll
        for (int r=0;r<8;r++){
            int l = tid + r*128;
            int cc = l>>6, oo = l&63;
            q_sm[cc][oo] = qb[(size_t)(d0+cc)*T_ + t0+oo];
        }
#pragma unroll
        for (int r=0;r<16;r++){
            int l = tid + r*128;
            int cc = l>>7, ss = l&127;
            k_sm[cc][ss] = kb[(size_t)(d0+cc)*T_ + s0+ss];
        }
        __syncthreads();
#pragma unroll
        for (int cc=0;cc<16;cc++){
            float wr[8];
#pragma unroll
            for (int i=0;i<8;i++) wr[i]=q_sm[cc][wy*8+i];
#pragma unroll
            for (int j=0;j<8;j++){
                float xv = k_sm[cc][wx+16*j];
#pragma unroll
                for (int i=0;i<8;i++) acc[i][j] += wr[i]*xv;
            }
        }
        __syncthreads();
    }
#pragma unroll
    for (int i=0;i<8;i++){
        float* prow = P + ((size_t)bh*T_ + t0+wy*8+i)*T_ + s0;
#pragma unroll
        for (int j=0;j<8;j++) prow[wx+16*j]=acc[i][j];
    }
}

/* ---------------- banded relative-K logits ---------------- */
__global__ void k_relband(const float* __restrict__ Q, const float* __restrict__ erk,
                          float* __restrict__ P)
{
    const int bh = blockIdx.y;
    const int t = blockIdx.x*8 + (threadIdx.x>>5);
    const int lane = threadIdx.x & 31;
    const float* qb = Q + (size_t)bh*64*T_;
    float q0 = qb[(size_t)lane*T_ + t];
    float q1 = qb[(size_t)(lane+32)*T_ + t];
    float* prow = P + ((size_t)bh*T_ + t)*T_;
    for (int r=0;r<21;r++){
        float pd = q0*erk[r*64+lane] + q1*erk[r*64+32+lane];
#pragma unroll
        for (int o=16;o;o>>=1) pd += __shfl_xor_sync(0xffffffffu, pd, o);
        int s = t + r - WIN_;
        if (lane==0 && (unsigned)s < (unsigned)T_) prow[s] += pd;
    }
}

/* ---------------- row softmax with mask ---------------- */
__launch_bounds__(256)
__global__ void k_softmax(float* __restrict__ P, const float* __restrict__ mask)
{
    const int row = blockIdx.x;
    const int t  = row & (T_-1);
    const int bh = row >> 9;
    const int b  = bh >> 3;
    float* p = P + (size_t)row*T_;
    const float* mb = mask + b*T_;
    const int tid = threadIdx.x;
    const float mt = mb[t];
    float v0 = (mt*mb[tid]     != 0.f) ? p[tid]     : -1e4f;
    float v1 = (mt*mb[tid+256] != 0.f) ? p[tid+256] : -1e4f;
    __shared__ float red[256];
    red[tid] = fmaxf(v0,v1);
    __syncthreads();
    for (int o=128;o>0;o>>=1){
        if (tid<o) red[tid]=fmaxf(red[tid],red[tid+o]);
        __syncthreads();
    }
    float mx = red[0];
    __syncthreads();
    float e0 = expf(v0-mx), e1 = expf(v1-mx);
    red[tid]=e0+e1;
    __syncthreads();
    for (int o=128;o>0;o>>=1){
        if (tid<o) red[tid]+=red[tid+o];
        __syncthreads();
    }
    float inv = 1.f/red[0];
    p[tid]=e0*inv; p[tid+256]=e1*inv;
}

/* ---------------- ctx = p @ v (+ banded rel-V) ---------------- */
__launch_bounds__(128)
__global__ void k_ctx(const float* __restrict__ P, const float* __restrict__ V,
                      const float* __restrict__ erv, float* __restrict__ CTX)
{
    const int t0 = blockIdx.x*128;
    const int bh = blockIdx.y;
    const float* vb = V + (size_t)bh*64*T_;
    const float* pb = P + (size_t)bh*T_*T_;
    __shared__ float w_sm[16][65];
    __shared__ float x_sm[16][129];
    const int tid = threadIdx.x;
    const int wx = tid&15, wy = tid>>4;
    float acc[8][8];
#pragma unroll
    for (int i=0;i<8;i++)
#pragma unroll
        for (int j=0;j<8;j++) acc[i][j]=0.f;

    for (int s0=0;s0<T_;s0+=16){
#pragma unroll
        for (int r=0;r<8;r++){
            int l = tid + r*128;
            int oo = l>>4, cc = l&15;
            w_sm[cc][oo] = vb[(size_t)oo*T_ + s0+cc];
        }
#pragma unroll
        for (int r=0;r<16;r++){
            int l = tid + r*128;
            int tt = l>>4, ss = l&15;
            x_sm[ss][tt] = pb[(size_t)(t0+tt)*T_ + s0+ss];
        }
        __syncthreads();
#pragma unroll
        for (int cc=0;cc<16;cc++){
            float wr[8];
#pragma unroll
            for (int i=0;i<8;i++) wr[i]=w_sm[cc][wy*8+i];
#pragma unroll
            for (int j=0;j<8;j++){
                float xv = x_sm[cc][wx+16*j];
#pragma unroll
                for (int i=0;i<8;i++) acc[i][j]+=wr[i]*xv;
            }
        }
        __syncthreads();
    }
#pragma unroll
    for (int j=0;j<8;j++){
        int t = t0 + wx + 16*j;
        for (int r=0;r<21;r++){
            int s = t + r - WIN_;
            if ((unsigned)s < (unsigned)T_){
                float pv = pb[(size_t)t*T_ + s];
#pragma unroll
                for (int i=0;i<8;i++) acc[i][j] += pv*erv[r*64 + wy*8+i];
            }
        }
    }
#pragma unroll
    for (int i=0;i<8;i++){
        float* crow = CTX + (size_t)(bh*64 + wy*8+i)*T_ + t0;
#pragma unroll
        for (int j=0;j<8;j++) crow[wx+16*j]=acc[i][j];
    }
}

/* ---------------- residual add + channel LayerNorm (in place on X) ---------------- */
__launch_bounds__(512)
__global__ void k_addln(float* __restrict__ X, const float* __restrict__ Yv,
                        const float* __restrict__ gamma, const float* __restrict__ beta)
{
    const int b = blockIdx.y;
    const int tl = threadIdx.x & 31;
    const int slot = threadIdx.x >> 5;
    const int t = blockIdx.x*32 + tl;
    __shared__ float ssum[16][33];
    __shared__ float ssq[16][33];
    float vals[32];
    float s=0.f, q=0.f;
    size_t base = (size_t)b*C_*T_ + t;
#pragma unroll
    for (int u=0;u<32;u++){
        int c = slot*32+u;
        float v = X[base + (size_t)c*T_] + Yv[base + (size_t)c*T_];
        vals[u]=v; s+=v; q+=v*v;
    }
    ssum[slot][tl]=s; ssq[slot][tl]=q;
    __syncthreads();
    float m=0.f, vv=0.f;
#pragma unroll
    for (int k2=0;k2<16;k2++){ m+=ssum[k2][tl]; vv+=ssq[k2][tl]; }
    m *= (1.f/512.f);
    vv = vv*(1.f/512.f) - m*m;
    float r = rsqrtf(vv + 1e-5f);
#pragma unroll
    for (int u=0;u<32;u++){
        int c = slot*32+u;
        X[base + (size_t)c*T_] = (vals[u]-m)*r*gamma[c] + beta[c];
    }
}

/* ---------------- host orchestration ---------------- */
extern "C" void kernel_launch(void* const* d_in, const int* in_sizes, int n_in,
                              void* d_out, int out_size)
{
    (void)in_sizes; (void)n_in; (void)out_size;
    const float* x_in = (const float*)d_in[0];
    const float* mask = (const float*)d_in[1];
    const float* Wq  = (const float*)d_in[2];
    const float* bq  = (const float*)d_in[3];
    const float* Wk  = (const float*)d_in[4];
    const float* bk  = (const float*)d_in[5];
    const float* Wv  = (const float*)d_in[6];
    const float* bv  = (const float*)d_in[7];
    const float* Wo  = (const float*)d_in[8];
    const float* bo  = (const float*)d_in[9];
    const float* erk = (const float*)d_in[10];
    const float* erv = (const float*)d_in[11];
    const float* g1  = (const float*)d_in[12];
    const float* b1  = (const float*)d_in[13];
    const float* g2  = (const float*)d_in[14];
    const float* b2  = (const float*)d_in[15];
    const float* W1  = (const float*)d_in[16];
    const float* bf1 = (const float*)d_in[17];
    const float* W2  = (const float*)d_in[18];
    const float* bf2 = (const float*)d_in[19];

    float* pool = 0;
    cudaGetSymbolAddress((void**)&pool, g_pool);
    float* px = pool;
    float* pq = pool + (size_t)1*ELT_X;
    float* pk = pool + (size_t)2*ELT_X;
    float* pv = pool + (size_t)3*ELT_X;
    float* pc = pool + (size_t)4*ELT_X;
    float* py = pool + (size_t)5*ELT_X;
    float* pp  = pool + (size_t)6*ELT_X;
    float* pxp = pool + (size_t)6*ELT_X + ELT_P;
    float* php = pool + (size_t)6*ELT_X + ELT_P + ELT_XP;

    k_maskmul<<<ELT_X/256,256>>>(x_in, mask, px);
    k_zb<<<(B_*C_+B_*F_)/256,256>>>(pxp, php);

    for (int L=0;L<6;L++){
        const float* wq = Wq + (size_t)L*C_*C_;
        const float* wk = Wk + (size_t)L*C_*C_;
        const float* wv = Wv + (size_t)L*C_*C_;
        const float* wo = Wo + (size_t)L*C_*C_;
        const float* w1 = W1 + (size_t)L*F_*C_*3;
        const float* w2 = W2 + (size_t)L*C_*F_*3;

        g_qkv<<<dim3(T_/128, 12, B_),256>>>(px, wq, wk, wv,
                                            bq+L*C_, bk+L*C_, bv+L*C_,
                                            pq, pk, pv);
        k_scores<<<dim3(T_/128, T_/64, B_*H_),128>>>(pq, pk, pp);
        k_relband<<<dim3(T_/8, B_*H_),256>>>(pq, erk + L*21*64, pp);
        k_softmax<<<B_*H_*T_,256>>>(pp, mask);
        k_ctx<<<dim3(T_/128, B_*H_),128>>>(pp, pv, erv + L*21*64, pc);
        g1x1<<<dim3(T_/128, C_/128, B_),256>>>(pc, wo, bo + L*C_, py, C_, C_, 1.f);
        k_addln<<<dim3(T_/32,B_),512>>>(px, py, g1+L*C_, b1+L*C_);

        k_pad<<<ELT_X/256,256>>>(px, mask, pxp);
        gconv3p<<<dim3(T_/128, F_/128, B_),256>>>(pxp, w1, bf1+L*F_, mask, php,
                                                  C_, F_, 0, (C_*3)/16);
        gconv3p<<<dim3(T_/128, C_/128, 2*B_),256>>>(php, w2, bf2+L*C_, mask, pq,
                                                    F_, C_, 1, (F_*3)/32);
        k_red<<<ELT_X/256,256>>>(pq, bf2+L*C_, mask, py);
        k_addln<<<dim3(T_/32,B_),512>>>(px, py, g2+L*C_, b2+L*C_);
    }
    k_maskmul<<<ELT_X/256,256>>>(px, mask, (float*)d_out);
}

// round 4
// speedup vs baseline: 3.0158x; 1.4952x over previous
#include <cuda_runtime.h>
#include <math.h>

#define B_ 8
#define T_ 512
#define C_ 512
#define H_ 8
#define F_ 2048
#define WIN_ 10
#define TP_ 516

#define ELT_X (B_*C_*T_)
#define ELT_P (B_*H_*T_*T_)
#define ELT_XP (B_*C_*TP_)
#define ELT_HP (B_*F_*TP_)

__device__ float g_pool[(size_t)6*ELT_X + ELT_P + ELT_XP + ELT_HP];

__device__ __forceinline__ unsigned f2tf(float x){
    unsigned y; asm("cvt.rna.tf32.f32 %0, %1;" : "=r"(y) : "f"(x)); return y;
}
__device__ __forceinline__ void mma_tf32(float c[4], const unsigned a[4], const unsigned b[2]){
    asm("mma.sync.aligned.m16n8k8.row.col.f32.tf32.tf32.f32 "
        "{%0,%1,%2,%3}, {%4,%5,%6,%7}, {%8,%9}, {%0,%1,%2,%3};"
        : "+f"(c[0]), "+f"(c[1]), "+f"(c[2]), "+f"(c[3])
        : "r"(a[0]), "r"(a[1]), "r"(a[2]), "r"(a[3]), "r"(b[0]), "r"(b[1]));
}
__device__ __forceinline__ float4 ld4(const float* p){ return *(const float4*)p; }
__device__ __forceinline__ void st4tf(float* p, float4 v){
    float4 w;
    w.x=__uint_as_float(f2tf(v.x)); w.y=__uint_as_float(f2tf(v.y));
    w.z=__uint_as_float(f2tf(v.z)); w.w=__uint_as_float(f2tf(v.w));
    *(float4*)p = w;
}

/* ---------------- elementwise mask ---------------- */
__global__ void k_maskmul(const float* __restrict__ X, const float* __restrict__ mask,
                          float* __restrict__ Y)
{
    int i = blockIdx.x*256 + threadIdx.x;
    int t = i & (T_-1);
    int b = i / (C_*T_);
    Y[i] = X[i] * mask[b*T_ + t];
}

/* ---------------- zero pad borders of pxp / php once ---------------- */
__global__ void k_zb(float* __restrict__ Xp, float* __restrict__ Hp)
{
    int r = blockIdx.x*256 + threadIdx.x;
    float* base = (r < B_*C_) ? (Xp + (size_t)r*TP_) : (Hp + (size_t)(r - B_*C_)*TP_);
    base[0]=0.f; base[513]=0.f; base[514]=0.f; base[515]=0.f;
}

/* =========== 1x1 GEMM: Y[b,o,t] = alpha*(W X + bias) ============ */
__launch_bounds__(256,2)
__global__ void g1x1(const float* __restrict__ X, const float* __restrict__ Wm,
                     const float* __restrict__ bias, float* __restrict__ Y,
                     int Cin, int Cout, float alpha)
{
    const int n0 = blockIdx.x*128;
    const int m0 = blockIdx.y*128;
    const int b  = blockIdx.z;
    const int tid = threadIdx.x;
    const int lane = tid & 31, wid = tid >> 5;
    const int gid = lane >> 2, tig = lane & 3;
    const int wm = wid & 1, wn = wid >> 1;

    __shared__ float smA[2][128][20];
    __shared__ float smB[2][16][136];

    const float* xb = X + (size_t)b*Cin*T_;
    const int rowA = tid >> 1, colA = (tid & 1)*8;
    const int rowB = tid >> 4, colB = (tid & 15)*8;

    float acc[4][4][4];
#pragma unroll
    for (int i=0;i<4;i++)
#pragma unroll
        for (int j=0;j<4;j++)
#pragma unroll
            for (int u=0;u<4;u++) acc[i][j][u]=0.f;

    const int KT = Cin/16;
    float4 pa0, pa1, pb0, pb1;
    {
        const float* ap = Wm + (size_t)(m0+rowA)*Cin + colA;
        pa0=ld4(ap); pa1=ld4(ap+4);
        const float* bp = xb + (size_t)rowB*T_ + n0 + colB;
        pb0=ld4(bp); pb1=ld4(bp+4);
        st4tf(&smA[0][rowA][colA], pa0); st4tf(&smA[0][rowA][colA+4], pa1);
        st4tf(&smB[0][rowB][colB], pb0); st4tf(&smB[0][rowB][colB+4], pb1);
    }
    __syncthreads();

    for (int kt=0; kt<KT; kt++){
        const int cur = kt & 1, nxt = cur ^ 1;
        const bool has = (kt+1 < KT);
        if (has){
            const int K0 = (kt+1)*16;
            const float* ap = Wm + (size_t)(m0+rowA)*Cin + K0 + colA;
            pa0=ld4(ap); pa1=ld4(ap+4);
            const float* bp = xb + (size_t)(K0+rowB)*T_ + n0 + colB;
            pb0=ld4(bp); pb1=ld4(bp+4);
        }
#pragma unroll
        for (int ks=0;ks<2;ks++){
            unsigned af[4][4], bf[4][2];
#pragma unroll
            for (int i=0;i<4;i++){
                int r = wm*64 + i*16 + gid;
                af[i][0]=__float_as_uint(smA[cur][r  ][ks*8+tig  ]);
                af[i][1]=__float_as_uint(smA[cur][r+8][ks*8+tig  ]);
                af[i][2]=__float_as_uint(smA[cur][r  ][ks*8+tig+4]);
                af[i][3]=__float_as_uint(smA[cur][r+8][ks*8+tig+4]);
            }
#pragma unroll
            for (int j=0;j<4;j++){
                int c = wn*32 + j*8 + gid;
                bf[j][0]=__float_as_uint(smB[cur][ks*8+tig  ][c]);
                bf[j][1]=__float_as_uint(smB[cur][ks*8+tig+4][c]);
            }
#pragma unroll
            for (int i=0;i<4;i++)
#pragma unroll
                for (int j=0;j<4;j++) mma_tf32(acc[i][j], af[i], bf[j]);
        }
        if (has){
            st4tf(&smA[nxt][rowA][colA], pa0); st4tf(&smA[nxt][rowA][colA+4], pa1);
            st4tf(&smB[nxt][rowB][colB], pb0); st4tf(&smB[nxt][rowB][colB+4], pb1);
        }
        __syncthreads();
    }

#pragma unroll
    for (int i=0;i<4;i++){
        int row = m0 + wm*64 + i*16 + gid;
        float bv0 = bias[row], bv8 = bias[row+8];
        float* y0 = Y + (size_t)(b*Cout + row)*T_;
        float* y8 = Y + (size_t)(b*Cout + row+8)*T_;
#pragma unroll
        for (int j=0;j<4;j++){
            int col = n0 + wn*32 + j*8 + tig*2;
            *(float2*)(y0+col)=make_float2(alpha*(acc[i][j][0]+bv0), alpha*(acc[i][j][1]+bv0));
            *(float2*)(y8+col)=make_float2(alpha*(acc[i][j][2]+bv8), alpha*(acc[i][j][3]+bv8));
        }
    }
}

/* =========== fused Q/K/V projection. Q -> [bh][t][d], K -> [c][t], V -> [bh][s][d] == */
__launch_bounds__(256,2)
__global__ void g_qkv(const float* __restrict__ X,
                      const float* __restrict__ Wq, const float* __restrict__ Wk, const float* __restrict__ Wv,
                      const float* __restrict__ bq, const float* __restrict__ bk, const float* __restrict__ bv,
                      float* __restrict__ Yq, float* __restrict__ Yk, float* __restrict__ Yv)
{
    const int n0 = blockIdx.x*128;
    const int mi = blockIdx.y;
    const int sel = mi >> 2;
    const int m0 = (mi & 3)*128;
    const int b  = blockIdx.z;
    const float* Wm  = (sel==0)?Wq:(sel==1)?Wk:Wv;
    const float* bias= (sel==0)?bq:(sel==1)?bk:bv;
    const float alpha= (sel==0)?0.125f:1.f;

    const int tid = threadIdx.x;
    const int lane = tid & 31, wid = tid >> 5;
    const int gid = lane >> 2, tig = lane & 3;
    const int wm = wid & 1, wn = wid >> 1;

    __shared__ float smA[2][128][20];
    __shared__ float smB[2][16][136];

    const float* xb = X + (size_t)b*C_*T_;
    const int rowA = tid >> 1, colA = (tid & 1)*8;
    const int rowB = tid >> 4, colB = (tid & 15)*8;

    float acc[4][4][4];
#pragma unroll
    for (int i=0;i<4;i++)
#pragma unroll
        for (int j=0;j<4;j++)
#pragma unroll
            for (int u=0;u<4;u++) acc[i][j][u]=0.f;

    const int KT = C_/16;
    float4 pa0, pa1, pb0, pb1;
    {
        const float* ap = Wm + (size_t)(m0+rowA)*C_ + colA;
        pa0=ld4(ap); pa1=ld4(ap+4);
        const float* bp = xb + (size_t)rowB*T_ + n0 + colB;
        pb0=ld4(bp); pb1=ld4(bp+4);
        st4tf(&smA[0][rowA][colA], pa0); st4tf(&smA[0][rowA][colA+4], pa1);
        st4tf(&smB[0][rowB][colB], pb0); st4tf(&smB[0][rowB][colB+4], pb1);
    }
    __syncthreads();

    for (int kt=0; kt<KT; kt++){
        const int cur = kt & 1, nxt = cur ^ 1;
        const bool has = (kt+1 < KT);
        if (has){
            const int K0 = (kt+1)*16;
            const float* ap = Wm + (size_t)(m0+rowA)*C_ + K0 + colA;
            pa0=ld4(ap); pa1=ld4(ap+4);
            const float* bp = xb + (size_t)(K0+rowB)*T_ + n0 + colB;
            pb0=ld4(bp); pb1=ld4(bp+4);
        }
#pragma unroll
        for (int ks=0;ks<2;ks++){
            unsigned af[4][4], bf[4][2];
#pragma unroll
            for (int i=0;i<4;i++){
                int r = wm*64 + i*16 + gid;
                af[i][0]=__float_as_uint(smA[cur][r  ][ks*8+tig  ]);
                af[i][1]=__float_as_uint(smA[cur][r+8][ks*8+tig  ]);
                af[i][2]=__float_as_uint(smA[cur][r  ][ks*8+tig+4]);
                af[i][3]=__float_as_uint(smA[cur][r+8][ks*8+tig+4]);
            }
#pragma unroll
            for (int j=0;j<4;j++){
                int c = wn*32 + j*8 + gid;
                bf[j][0]=__float_as_uint(smB[cur][ks*8+tig  ][c]);
                bf[j][1]=__float_as_uint(smB[cur][ks*8+tig+4][c]);
            }
#pragma unroll
            for (int i=0;i<4;i++)
#pragma unroll
                for (int j=0;j<4;j++) mma_tf32(acc[i][j], af[i], bf[j]);
        }
        if (has){
            st4tf(&smA[nxt][rowA][colA], pa0); st4tf(&smA[nxt][rowA][colA+4], pa1);
            st4tf(&smB[nxt][rowB][colB], pb0); st4tf(&smB[nxt][rowB][colB+4], pb1);
        }
        __syncthreads();
    }

    if (sel==1){
#pragma unroll
        for (int i=0;i<4;i++){
            int row = m0 + wm*64 + i*16 + gid;
            float bv0 = bias[row], bv8 = bias[row+8];
            float* y0 = Yk + (size_t)(b*C_ + row)*T_;
            float* y8 = Yk + (size_t)(b*C_ + row+8)*T_;
#pragma unroll
            for (int j=0;j<4;j++){
                int col = n0 + wn*32 + j*8 + tig*2;
                *(float2*)(y0+col)=make_float2(acc[i][j][0]+bv0, acc[i][j][1]+bv0);
                *(float2*)(y8+col)=make_float2(acc[i][j][2]+bv8, acc[i][j][3]+bv8);
            }
        }
    } else {
        float* Yt = (sel==0)?Yq:Yv;
#pragma unroll
        for (int i=0;i<4;i++){
            int row = m0 + wm*64 + i*16 + gid;
            float bv0 = bias[row], bv8 = bias[row+8];
            int h0 = row>>6, d0v = row&63;
            int h8 = (row+8)>>6, d8v = (row+8)&63;
            float* base0 = Yt + ((size_t)(b*H_+h0)*T_)*64 + d0v;
            float* base8 = Yt + ((size_t)(b*H_+h8)*T_)*64 + d8v;
#pragma unroll
            for (int j=0;j<4;j++){
                int col = n0 + wn*32 + j*8 + tig*2;
                base0[(size_t)col*64]     = alpha*(acc[i][j][0]+bv0);
                base0[(size_t)(col+1)*64] = alpha*(acc[i][j][1]+bv0);
                base8[(size_t)col*64]     = alpha*(acc[i][j][2]+bv8);
                base8[(size_t)(col+1)*64] = alpha*(acc[i][j][3]+bv8);
            }
        }
    }
}

/* =========== MMA scores: P[bh,t,s] = sum_d Qt[bh,t,d]*K[bh,d,s] ============ */
__launch_bounds__(256,2)
__global__ void g_sc(const float* __restrict__ Qt, const float* __restrict__ Kc,
                     float* __restrict__ P)
{
    const int s0 = blockIdx.x*128;
    const int t0 = blockIdx.y*128;
    const int bh = blockIdx.z;
    const int tid = threadIdx.x;
    const int lane = tid & 31, wid = tid >> 5;
    const int gid = lane >> 2, tig = lane & 3;
    const int wm = wid & 1, wn = wid >> 1;

    __shared__ float smA[2][128][20];
    __shared__ float smB[2][16][136];

    const float* qb = Qt + (size_t)bh*T_*64;
    const float* kb = Kc + (size_t)bh*64*T_;
    const int rowA = tid >> 1, colA = (tid & 1)*8;
    const int rowB = tid >> 4, colB = (tid & 15)*8;

    float acc[4][4][4];
#pragma unroll
    for (int i=0;i<4;i++)
#pragma unroll
        for (int j=0;j<4;j++)
#pragma unroll
            for (int u=0;u<4;u++) acc[i][j][u]=0.f;

    float4 pa0, pa1, pb0, pb1;
    {
        const float* ap = qb + (size_t)(t0+rowA)*64 + colA;
        pa0=ld4(ap); pa1=ld4(ap+4);
        const float* bp = kb + (size_t)rowB*T_ + s0 + colB;
        pb0=ld4(bp); pb1=ld4(bp+4);
        st4tf(&smA[0][rowA][colA], pa0); st4tf(&smA[0][rowA][colA+4], pa1);
        st4tf(&smB[0][rowB][colB], pb0); st4tf(&smB[0][rowB][colB+4], pb1);
    }
    __syncthreads();

    for (int kt=0; kt<4; kt++){
        const int cur = kt & 1, nxt = cur ^ 1;
        const bool has = (kt+1 < 4);
        if (has){
            const int K0 = (kt+1)*16;
            const float* ap = qb + (size_t)(t0+rowA)*64 + K0 + colA;
            pa0=ld4(ap); pa1=ld4(ap+4);
            const float* bp = kb + (size_t)(K0+rowB)*T_ + s0 + colB;
            pb0=ld4(bp); pb1=ld4(bp+4);
        }
#pragma unroll
        for (int ks=0;ks<2;ks++){
            unsigned af[4][4], bf[4][2];
#pragma unroll
            for (int i=0;i<4;i++){
                int r = wm*64 + i*16 + gid;
                af[i][0]=__float_as_uint(smA[cur][r  ][ks*8+tig  ]);
                af[i][1]=__float_as_uint(smA[cur][r+8][ks*8+tig  ]);
                af[i][2]=__float_as_uint(smA[cur][r  ][ks*8+tig+4]);
                af[i][3]=__float_as_uint(smA[cur][r+8][ks*8+tig+4]);
            }
#pragma unroll
            for (int j=0;j<4;j++){
                int c = wn*32 + j*8 + gid;
                bf[j][0]=__float_as_uint(smB[cur][ks*8+tig  ][c]);
                bf[j][1]=__float_as_uint(smB[cur][ks*8+tig+4][c]);
            }
#pragma unroll
            for (int i=0;i<4;i++)
#pragma unroll
                for (int j=0;j<4;j++) mma_tf32(acc[i][j], af[i], bf[j]);
        }
        if (has){
            st4tf(&smA[nxt][rowA][colA], pa0); st4tf(&smA[nxt][rowA][colA+4], pa1);
            st4tf(&smB[nxt][rowB][colB], pb0); st4tf(&smB[nxt][rowB][colB+4], pb1);
        }
        __syncthreads();
    }

#pragma unroll
    for (int i=0;i<4;i++){
        int row = t0 + wm*64 + i*16 + gid;
        float* y0 = P + ((size_t)bh*T_ + row)*T_;
        float* y8 = P + ((size_t)bh*T_ + row+8)*T_;
#pragma unroll
        for (int j=0;j<4;j++){
            int col = s0 + wn*32 + j*8 + tig*2;
            *(float2*)(y0+col)=make_float2(acc[i][j][0], acc[i][j][1]);
            *(float2*)(y8+col)=make_float2(acc[i][j][2], acc[i][j][3]);
        }
    }
}

/* =========== MMA ctx: CTX[c][t] = sum_s P[t][s] Vt[s][d] + rel-V band ============ */
__launch_bounds__(256,2)
__global__ void g_ctx(const float* __restrict__ P, const float* __restrict__ Vt,
                      const float* __restrict__ erv, float* __restrict__ CTX)
{
    const int t0 = blockIdx.x*128;
    const int bh = blockIdx.y;
    const int b  = bh >> 3, h = bh & 7;
    const int tid = threadIdx.x;
    const int lane = tid & 31, wid = tid >> 5;
    const int gid = lane >> 2, tig = lane & 3;
    const int wm = wid & 1, wn = wid >> 1;   /* wn in 0..3, 16 n each */

    __shared__ float smA[2][128][20];
    __shared__ float smB[2][16][72];
    __shared__ float sErv[21*64];

    const float* pb = P + (size_t)bh*T_*T_;
    const float* vb = Vt + (size_t)bh*T_*64;
    const int rowA = tid >> 1, colA = (tid & 1)*8;
    const int rowB = tid >> 4, colB = (tid & 15)*4;

    for (int l=tid; l<21*64; l+=256) sErv[l]=erv[l];

    float acc[4][2][4];
#pragma unroll
    for (int i=0;i<4;i++)
#pragma unroll
        for (int j=0;j<2;j++)
#pragma unroll
            for (int u=0;u<4;u++) acc[i][j][u]=0.f;

    float4 pa0, pa1, pb0;
    {
        const float* ap = pb + (size_t)(t0+rowA)*T_ + colA;
        pa0=ld4(ap); pa1=ld4(ap+4);
        const float* bp = vb + (size_t)rowB*64 + colB;
        pb0=ld4(bp);
        st4tf(&smA[0][rowA][colA], pa0); st4tf(&smA[0][rowA][colA+4], pa1);
        st4tf(&smB[0][rowB][colB], pb0);
    }
    __syncthreads();

    const int KT = T_/16;
    for (int kt=0; kt<KT; kt++){
        const int cur = kt & 1, nxt = cur ^ 1;
        const bool has = (kt+1 < KT);
        if (has){
            const int K0 = (kt+1)*16;
            const float* ap = pb + (size_t)(t0+rowA)*T_ + K0 + colA;
            pa0=ld4(ap); pa1=ld4(ap+4);
            const float* bp = vb + (size_t)(K0+rowB)*64 + colB;
            pb0=ld4(bp);
        }
#pragma unroll
        for (int ks=0;ks<2;ks++){
            unsigned af[4][4], bf[2][2];
#pragma unroll
            for (int i=0;i<4;i++){
                int r = wm*64 + i*16 + gid;
                af[i][0]=__float_as_uint(smA[cur][r  ][ks*8+tig  ]);
                af[i][1]=__float_as_uint(smA[cur][r+8][ks*8+tig  ]);
                af[i][2]=__float_as_uint(smA[cur][r  ][ks*8+tig+4]);
                af[i][3]=__float_as_uint(smA[cur][r+8][ks*8+tig+4]);
            }
#pragma unroll
            for (int j=0;j<2;j++){
                int c = wn*16 + j*8 + gid;
                bf[j][0]=__float_as_uint(smB[cur][ks*8+tig  ][c]);
                bf[j][1]=__float_as_uint(smB[cur][ks*8+tig+4][c]);
            }
#pragma unroll
            for (int i=0;i<4;i++)
#pragma unroll
                for (int j=0;j<2;j++) mma_tf32(acc[i][j], af[i], bf[j]);
        }
        if (has){
            st4tf(&smA[nxt][rowA][colA], pa0); st4tf(&smA[nxt][rowA][colA+4], pa1);
            st4tf(&smB[nxt][rowB][colB], pb0);
        }
        __syncthreads();
    }

    /* banded rel-V */
#pragma unroll
    for (int i=0;i<4;i++){
#pragma unroll
        for (int rr=0; rr<2; rr++){
            int t = t0 + wm*64 + i*16 + gid + rr*8;
            const float* prow = pb + (size_t)t*T_;
            for (int r=0;r<21;r++){
                int s = t + r - WIN_;
                if ((unsigned)s < (unsigned)T_){
                    float pv = prow[s];
#pragma unroll
                    for (int j=0;j<2;j++){
                        int d = wn*16 + j*8 + tig*2;
                        acc[i][j][rr*2+0] += pv*sErv[r*64 + d];
                        acc[i][j][rr*2+1] += pv*sErv[r*64 + d+1];
                    }
                }
            }
        }
    }

    /* store transposed: CTX[b][h*64+d][t] */
#pragma unroll
    for (int i=0;i<4;i++){
        int row = t0 + wm*64 + i*16 + gid;
#pragma unroll
        for (int j=0;j<2;j++){
            int d = wn*16 + j*8 + tig*2;
            float* c0 = CTX + (size_t)(b*C_ + h*64 + d)*T_;
            float* c1 = CTX + (size_t)(b*C_ + h*64 + d+1)*T_;
            c0[row]   = acc[i][j][0];
            c1[row]   = acc[i][j][1];
            c0[row+8] = acc[i][j][2];
            c1[row+8] = acc[i][j][3];
        }
    }
}

/* =========== K=3 conv GEMM on padded pre-masked input =========== */
__launch_bounds__(256,2)
__global__ void gconv3p(const float* __restrict__ Xp, const float* __restrict__ Wm,
                        const float* __restrict__ bias, const float* __restrict__ mask,
                        float* __restrict__ Y, int Cin, int Cout,
                        int mode, int ktiles)
{
    const int n0 = blockIdx.x*128;
    const int m0 = blockIdx.y*128;
    const int bz = blockIdx.z;
    const int b    = (mode==1) ? (bz & 7) : bz;
    const int part = (mode==1) ? (bz >> 3) : 0;
    const int kOff = part*(ktiles*16);

    const int tid = threadIdx.x;
    const int lane = tid & 31, wid = tid >> 5;
    const int gid = lane >> 2, tig = lane & 3;
    const int wm = wid & 1, wn = wid >> 1;

    __shared__ float smA[2][128][20];
    __shared__ float smB[2][16][136];

    const float* xpb = Xp + (size_t)b*Cin*TP_;
    const int Ktot = Cin*3;
    const int rowA = tid >> 1, colA = (tid & 1)*8;
    const int rowB = tid >> 4, colB = (tid & 15)*8;

    float acc[4][4][4];
#pragma unroll
    for (int i=0;i<4;i++)
#pragma unroll
        for (int j=0;j<4;j++)
#pragma unroll
            for (int u=0;u<4;u++) acc[i][j][u]=0.f;

    float4 pa0, pa1;
    float pbv[8];
    {
        const float* ap = Wm + (size_t)(m0+rowA)*Ktot + kOff + colA;
        pa0=ld4(ap); pa1=ld4(ap+4);
        int kg = kOff + rowB;
        int cc = kg/3, kk = kg - cc*3;
        const float* bp = xpb + (size_t)cc*TP_ + n0 + colB + kk;
#pragma unroll
        for (int u=0;u<8;u++) pbv[u]=bp[u];
        st4tf(&smA[0][rowA][colA], pa0); st4tf(&smA[0][rowA][colA+4], pa1);
        st4tf(&smB[0][rowB][colB], make_float4(pbv[0],pbv[1],pbv[2],pbv[3]));
        st4tf(&smB[0][rowB][colB+4], make_float4(pbv[4],pbv[5],pbv[6],pbv[7]));
    }
    __syncthreads();

    for (int kt=0; kt<ktiles; kt++){
        const int cur = kt & 1, nxt = cur ^ 1;
        const bool has = (kt+1 < ktiles);
        if (has){
            const int K0 = kOff + (kt+1)*16;
            const float* ap = Wm + (size_t)(m0+rowA)*Ktot + K0 + colA;
            pa0=ld4(ap); pa1=ld4(ap+4);
            int kg = K0 + rowB;
            int cc = kg/3, kk = kg - cc*3;
            const float* bp = xpb + (size_t)cc*TP_ + n0 + colB + kk;
#pragma unroll
            for (int u=0;u<8;u++) pbv[u]=bp[u];
        }
#pragma unroll
        for (int ks=0;ks<2;ks++){
            unsigned af[4][4], bf[4][2];
#pragma unroll
            for (int i=0;i<4;i++){
                int r = wm*64 + i*16 + gid;
                af[i][0]=__float_as_uint(smA[cur][r  ][ks*8+tig  ]);
                af[i][1]=__float_as_uint(smA[cur][r+8][ks*8+tig  ]);
                af[i][2]=__float_as_uint(smA[cur][r  ][ks*8+tig+4]);
                af[i][3]=__float_as_uint(smA[cur][r+8][ks*8+tig+4]);
            }
#pragma unroll
            for (int j=0;j<4;j++){
                int c = wn*32 + j*8 + gid;
                bf[j][0]=__float_as_uint(smB[cur][ks*8+tig  ][c]);
                bf[j][1]=__float_as_uint(smB[cur][ks*8+tig+4][c]);
            }
#pragma unroll
            for (int i=0;i<4;i++)
#pragma unroll
                for (int j=0;j<4;j++) mma_tf32(acc[i][j], af[i], bf[j]);
        }
        if (has){
            st4tf(&smA[nxt][rowA][colA], pa0); st4tf(&smA[nxt][rowA][colA+4], pa1);
            st4tf(&smB[nxt][rowB][colB], make_float4(pbv[0],pbv[1],pbv[2],pbv[3]));
            st4tf(&smB[nxt][rowB][colB+4], make_float4(pbv[4],pbv[5],pbv[6],pbv[7]));
        }
        __syncthreads();
    }

    if (mode==0){
        const float* mb = mask + b*T_;
#pragma unroll
        for (int i=0;i<4;i++){
            int row = m0 + wm*64 + i*16 + gid;
            float bv0 = bias[row], bv8 = bias[row+8];
            float* y0 = Y + (size_t)(b*Cout + row)*TP_ + 1;
            float* y8 = Y + (size_t)(b*Cout + row+8)*TP_ + 1;
#pragma unroll
            for (int j=0;j<4;j++){
                int col = n0 + wn*32 + j*8 + tig*2;
                float m0v = mb[col], m1v = mb[col+1];
                y0[col]   = fmaxf(acc[i][j][0]+bv0, 0.f)*m0v;
                y0[col+1] = fmaxf(acc[i][j][1]+bv0, 0.f)*m1v;
                y8[col]   = fmaxf(acc[i][j][2]+bv8, 0.f)*m0v;
                y8[col+1] = fmaxf(acc[i][j][3]+bv8, 0.f)*m1v;
            }
        }
    } else {
#pragma unroll
        for (int i=0;i<4;i++){
            int row = m0 + wm*64 + i*16 + gid;
            float* y0 = Y + (size_t)part*ELT_X + (size_t)(b*Cout + row)*T_;
            float* y8 = Y + (size_t)part*ELT_X + (size_t)(b*Cout + row+8)*T_;
#pragma unroll
            for (int j=0;j<4;j++){
                int col = n0 + wn*32 + j*8 + tig*2;
                *(float2*)(y0+col)=make_float2(acc[i][j][0], acc[i][j][1]);
                *(float2*)(y8+col)=make_float2(acc[i][j][2], acc[i][j][3]);
            }
        }
    }
}

/* ---------------- split-K reduce + bias + mask ---------------- */
__global__ void k_red(const float* __restrict__ P0, const float* __restrict__ bias,
                      const float* __restrict__ mask, float* __restrict__ Y)
{
    int i = blockIdx.x*256 + threadIdx.x;
    int t = i & (T_-1);
    int o = (i >> 9) & (C_-1);
    int b = i >> 18;
    Y[i] = (P0[i] + P0[(size_t)ELT_X + i] + bias[o]) * mask[b*T_ + t];
}

/* ---------------- banded relative-K logits (Qt layout) ---------------- */
__global__ void k_relband(const float* __restrict__ Qt, const float* __restrict__ erk,
                          float* __restrict__ P)
{
    const int bh = blockIdx.y;
    const int t = blockIdx.x*8 + (threadIdx.x>>5);
    const int lane = threadIdx.x & 31;
    const float* qr = Qt + ((size_t)bh*T_ + t)*64;
    float q0 = qr[lane];
    float q1 = qr[32+lane];
    float* prow = P + ((size_t)bh*T_ + t)*T_;
    for (int r=0;r<21;r++){
        float pd = q0*erk[r*64+lane] + q1*erk[r*64+32+lane];
#pragma unroll
        for (int o=16;o;o>>=1) pd += __shfl_xor_sync(0xffffffffu, pd, o);
        int s = t + r - WIN_;
        if (lane==0 && (unsigned)s < (unsigned)T_) prow[s] += pd;
    }
}

/* ---------------- row softmax with mask (shuffle reductions) ---------------- */
__launch_bounds__(256)
__global__ void k_softmax(float* __restrict__ P, const float* __restrict__ mask)
{
    const int row = blockIdx.x;
    const int t  = row & (T_-1);
    const int bh = row >> 9;
    const int b  = bh >> 3;
    float* p = P + (size_t)row*T_;
    const float* mb = mask + b*T_;
    const int tid = threadIdx.x;
    const int lane = tid & 31, w = tid >> 5;
    const float mt = mb[t];
    float v0 = (mt*mb[tid]     != 0.f) ? p[tid]     : -1e4f;
    float v1 = (mt*mb[tid+256] != 0.f) ? p[tid+256] : -1e4f;
    __shared__ float red[8];
    float m = fmaxf(v0,v1);
#pragma unroll
    for (int o=16;o;o>>=1) m = fmaxf(m, __shfl_xor_sync(0xffffffffu, m, o));
    if (lane==0) red[w]=m;
    __syncthreads();
    float mx = red[0];
#pragma unroll
    for (int k2=1;k2<8;k2++) mx = fmaxf(mx, red[k2]);
    float e0 = expf(v0-mx), e1 = expf(v1-mx);
    float s = e0+e1;
#pragma unroll
    for (int o=16;o;o>>=1) s += __shfl_xor_sync(0xffffffffu, s, o);
    __syncthreads();
    if (lane==0) red[w]=s;
    __syncthreads();
    float tot = 0.f;
#pragma unroll
    for (int k2=0;k2<8;k2++) tot += red[k2];
    float inv = 1.f/tot;
    p[tid]=e0*inv; p[tid+256]=e1*inv;
}

/* ---------------- residual add + channel LayerNorm (in place, optional pad out) ---- */
__launch_bounds__(512)
__global__ void k_addln(float* __restrict__ X, const float* __restrict__ Yv,
                        const float* __restrict__ gamma, const float* __restrict__ beta,
                        float* __restrict__ Xp, const float* __restrict__ mask)
{
    const int b = blockIdx.y;
    const int tl = threadIdx.x & 31;
    const int slot = threadIdx.x >> 5;
    const int t = blockIdx.x*32 + tl;
    __shared__ float ssum[16][33];
    __shared__ float ssq[16][33];
    float vals[32];
    float s=0.f, q=0.f;
    size_t base = (size_t)b*C_*T_ + t;
#pragma unroll
    for (int u=0;u<32;u++){
        int c = slot*32+u;
        float v = X[base + (size_t)c*T_] + Yv[base + (size_t)c*T_];
        vals[u]=v; s+=v; q+=v*v;
    }
    ssum[slot][tl]=s; ssq[slot][tl]=q;
    __syncthreads();
    float m=0.f, vv=0.f;
#pragma unroll
    for (int k2=0;k2<16;k2++){ m+=ssum[k2][tl]; vv+=ssq[k2][tl]; }
    m *= (1.f/512.f);
    vv = vv*(1.f/512.f) - m*m;
    float r = rsqrtf(vv + 1e-5f);
    float mk = Xp ? mask[b*T_ + t] : 0.f;
#pragma unroll
    for (int u=0;u<32;u++){
        int c = slot*32+u;
        float o = (vals[u]-m)*r*gamma[c] + beta[c];
        X[base + (size_t)c*T_] = o;
        if (Xp) Xp[((size_t)(b*C_+c))*TP_ + t + 1] = o*mk;
    }
}

/* ---------------- host orchestration ---------------- */
extern "C" void kernel_launch(void* const* d_in, const int* in_sizes, int n_in,
                              void* d_out, int out_size)
{
    (void)in_sizes; (void)n_in; (void)out_size;
    const float* x_in = (const float*)d_in[0];
    const float* mask = (const float*)d_in[1];
    const float* Wq  = (const float*)d_in[2];
    const float* bq  = (const float*)d_in[3];
    const float* Wk  = (const float*)d_in[4];
    const float* bk  = (const float*)d_in[5];
    const float* Wv  = (const float*)d_in[6];
    const float* bv  = (const float*)d_in[7];
    const float* Wo  = (const float*)d_in[8];
    const float* bo  = (const float*)d_in[9];
    const float* erk = (const float*)d_in[10];
    const float* erv = (const float*)d_in[11];
    const float* g1  = (const float*)d_in[12];
    const float* b1  = (const float*)d_in[13];
    const float* g2  = (const float*)d_in[14];
    const float* b2  = (const float*)d_in[15];
    const float* W1  = (const float*)d_in[16];
    const float* bf1 = (const float*)d_in[17];
    const float* W2  = (const float*)d_in[18];
    const float* bf2 = (const float*)d_in[19];

    float* pool = 0;
    cudaGetSymbolAddress((void**)&pool, g_pool);
    float* px = pool;
    float* pq = pool + (size_t)1*ELT_X;   /* Qt, also split-K part0 */
    float* pk = pool + (size_t)2*ELT_X;   /* K,  also split-K part1 */
    float* pv = pool + (size_t)3*ELT_X;   /* Vt */
    float* pc = pool + (size_t)4*ELT_X;
    float* py = pool + (size_t)5*ELT_X;
    float* pp  = pool + (size_t)6*ELT_X;
    float* pxp = pool + (size_t)6*ELT_X + ELT_P;
    float* php = pool + (size_t)6*ELT_X + ELT_P + ELT_XP;

    k_maskmul<<<ELT_X/256,256>>>(x_in, mask, px);
    k_zb<<<(B_*C_+B_*F_)/256,256>>>(pxp, php);

    for (int L=0;L<6;L++){
        const float* wq = Wq + (size_t)L*C_*C_;
        const float* wk = Wk + (size_t)L*C_*C_;
        const float* wv = Wv + (size_t)L*C_*C_;
        const float* wo = Wo + (size_t)L*C_*C_;
        const float* w1 = W1 + (size_t)L*F_*C_*3;
        const float* w2 = W2 + (size_t)L*C_*F_*3;

        g_qkv<<<dim3(T_/128, 12, B_),256>>>(px, wq, wk, wv,
                                            bq+L*C_, bk+L*C_, bv+L*C_,
                                            pq, pk, pv);
        g_sc<<<dim3(T_/128, T_/128, B_*H_),256>>>(pq, pk, pp);
        k_relband<<<dim3(T_/8, B_*H_),256>>>(pq, erk + L*21*64, pp);
        k_softmax<<<B_*H_*T_,256>>>(pp, mask);
        g_ctx<<<dim3(T_/128, B_*H_),256>>>(pp, pv, erv + L*21*64, pc);
        g1x1<<<dim3(T_/128, C_/128, B_),256>>>(pc, wo, bo + L*C_, py, C_, C_, 1.f);
        k_addln<<<dim3(T_/32,B_),512>>>(px, py, g1+L*C_, b1+L*C_, pxp, mask);

        gconv3p<<<dim3(T_/128, F_/128, B_),256>>>(pxp, w1, bf1+L*F_, mask, php,
                                                  C_, F_, 0, (C_*3)/16);
        gconv3p<<<dim3(T_/128, C_/128, 2*B_),256>>>(php, w2, bf2+L*C_, mask, pq,
                                                    F_, C_, 1, (F_*3)/32);
        k_red<<<ELT_X/256,256>>>(pq, bf2+L*C_, mask, py);
        k_addln<<<dim3(T_/32,B_),512>>>(px, py, g2+L*C_, b2+L*C_, (float*)0, mask);
    }
    k_maskmul<<<ELT_X/256,256>>>(px, mask, (float*)d_out);
}